// round 13
// baseline (speedup 1.0000x reference)
#include <cuda_runtime.h>
#include <math.h>

#define Bz 32
#define NFr 16
#define Dd 256
#define Ss 21
#define Nn 192
#define NA 20
#define EPSs 1e-8f
#define LN_EPS 1e-5f
#define RLN 24
#define RS 7

typedef unsigned long long u64;

// ---------------- packed f32x2 helpers ---------------------------------------
__device__ __forceinline__ void fma2(u64& d, u64 a, u64 b) {
    asm("fma.rn.f32x2 %0, %1, %2, %0;" : "+l"(d) : "l"(a), "l"(b));
}
__device__ __forceinline__ u64 dup2(float v) {
    u64 r; asm("mov.b64 %0, {%1, %1};" : "=l"(r) : "f"(v)); return r;
}
__device__ __forceinline__ float2 unpk(u64 v) {
    float lo, hi; asm("mov.b64 {%0, %1}, %2;" : "=f"(lo), "=f"(hi) : "l"(v));
    return make_float2(lo, hi);
}

// ---------------- scratch ----------------------------------------------------
__device__ float g_K[(size_t)Bz * NFr * Nn * Dd];
__device__ float4 g_V4[(size_t)Bz * NFr * (Nn / 4) * Dd];
__device__ float g_slots[Bz * Ss * Dd];
__device__ float g_At[Bz * Nn * Ss];
__device__ unsigned g_dots_done[Bz];
__device__ unsigned g_slot_done[Bz];
__device__ float4 g_WqT4[64 * Dd];
__device__ float4 g_WkT4[64 * Dd];
__device__ float4 g_WvT4[64 * Dd];
__device__ float4 g_W1T4[64 * Dd];
__device__ float4 g_W2T4[64 * Dd];
__device__ float4 g_WihT4[64 * 3 * Dd];
__device__ float4 g_WhhT4[64 * 3 * Dd];

__device__ __forceinline__ float4 ldcg4(const float4* p) { return __ldcg(p); }

// ---------------- sync helpers ------------------------------------------------
__device__ __forceinline__ void wait_ge(unsigned* p, unsigned tgt) {
    if (threadIdx.x == 0) {
        unsigned v;
        do {
            asm volatile("ld.acquire.gpu.global.u32 %0, [%1];"
                         : "=r"(v) : "l"(p) : "memory");
        } while (v < tgt);
    }
    __syncthreads();
}
__device__ __forceinline__ void signal(unsigned* p) {
    __syncthreads();
    if (threadIdx.x == 0) { __threadfence(); atomicAdd(p, 1u); }
}

// -------- setup: f4-transpose all weights + init slots + zero counters --------
__global__ void setup_kernel(const float* __restrict__ Wq, const float* __restrict__ Wk,
                             const float* __restrict__ Wv, const float* __restrict__ W1,
                             const float* __restrict__ W2, const float* __restrict__ Wih,
                             const float* __restrict__ Whh,
                             const float* __restrict__ noise,
                             const float* __restrict__ mu,
                             const float* __restrict__ sigma) {
    int bid = blockIdx.x;
    int tx = threadIdx.x, ty = threadIdx.y;
    if (bid < 176) {
        __shared__ float4 tile[32][33];
        const float4* src; float4* dst; int R; int tloc;
        if (bid < 80) {
            int m = bid / 16; tloc = bid % 16; R = 256;
            switch (m) {
                case 0: src = (const float4*)Wq; dst = g_WqT4; break;
                case 1: src = (const float4*)Wk; dst = g_WkT4; break;
                case 2: src = (const float4*)Wv; dst = g_WvT4; break;
                case 3: src = (const float4*)W1; dst = g_W1T4; break;
                default: src = (const float4*)W2; dst = g_W2T4; break;
            }
        } else {
            int m = (bid - 80) / 48; tloc = (bid - 80) % 48; R = 768;
            src = (const float4*)(m == 0 ? Wih : Whh);
            dst = (m == 0 ? g_WihT4 : g_WhhT4);
        }
        int bx = (tloc & 1) * 32;
        int by = (tloc >> 1) * 32;
        #pragma unroll
        for (int i = 0; i < 32; i += 8)
            tile[ty + i][tx] = src[(size_t)(by + ty + i) * 64 + bx + tx];
        __syncthreads();
        #pragma unroll
        for (int i = 0; i < 32; i += 8)
            dst[(size_t)(bx + ty + i) * R + by + tx] = tile[tx][ty + i];
    } else {
        int t = ty * 32 + tx;
        int base = (bid - 176) * 1024 + t;
        #pragma unroll
        for (int u = 0; u < 4; u++) {
            int idx = base + u * 256;
            int d = idx & (Dd - 1);
            g_slots[idx] = mu[d] + sigma[d] * noise[idx];
        }
        if (bid == 176 && t < Bz) { g_dots_done[t] = 0u; g_slot_done[t] = 0u; }
    }
}

// ---------------- warp helpers ------------------------------------------------
__device__ __forceinline__ float warp_sum(float v) {
    #pragma unroll
    for (int o = 16; o > 0; o >>= 1) v += __shfl_xor_sync(0xffffffffu, v, o);
    return v;
}
__device__ __forceinline__ float warp_max(float v) {
    #pragma unroll
    for (int o = 16; o > 0; o >>= 1) v = fmaxf(v, __shfl_xor_sync(0xffffffffu, v, o));
    return v;
}

// ------- LN(all frames) -> K, V4.  grid = B*NF*N/RLN = 4096 ------------------
__global__ __launch_bounds__(256)
void kv_all_kernel(const float* __restrict__ inputs,
                   const float* __restrict__ gam, const float* __restrict__ bet,
                   const float* __restrict__ bk, const float* __restrict__ bv) {
    __shared__ float2 xs2[RLN / 2][Dd];
    int row0 = blockIdx.x * RLN;
    int t = threadIdx.x, w = t >> 5, l = t & 31;

    for (int rr = w; rr < RLN; rr += 8) {
        int row = row0 + rr;
        const float* src = inputs + (size_t)row * Dd;
        float v[8]; float s = 0.f;
        #pragma unroll
        for (int u = 0; u < 8; u++) { v[u] = src[l + 32 * u]; s += v[u]; }
        s = warp_sum(s);
        float m = s * (1.0f / Dd);
        float vs = 0.f;
        #pragma unroll
        for (int u = 0; u < 8; u++) { v[u] -= m; vs += v[u] * v[u]; }
        vs = warp_sum(vs);
        float inv = rsqrtf(vs * (1.0f / Dd) + LN_EPS);
        int p = rr >> 1, e = rr & 1;
        #pragma unroll
        for (int u = 0; u < 8; u++) {
            int k = l + 32 * u;
            ((float*)xs2)[((size_t)p * Dd + k) * 2 + e] = v[u] * inv * gam[k] + bet[k];
        }
    }
    __syncthreads();

    int t2 = threadIdx.x;
    int c = t2;
    u64 aK[RLN / 2], aV[RLN / 2];
    #pragma unroll
    for (int p = 0; p < RLN / 2; p++) { aK[p] = 0ULL; aV[p] = 0ULL; }
    const float4* wk4 = g_WkT4 + c;
    const float4* wv4 = g_WvT4 + c;
    float4 ck = wk4[0], cv = wv4[0];
    for (int kq = 0; kq < 64; kq++) {
        int nx = (kq < 63 ? kq + 1 : 63) * Dd;
        float4 nk = wk4[nx], nv = wv4[nx];
        int k = 4 * kq;
        u64 dk0 = dup2(ck.x), dk1 = dup2(ck.y), dk2 = dup2(ck.z), dk3 = dup2(ck.w);
        u64 dv0 = dup2(cv.x), dv1 = dup2(cv.y), dv2 = dup2(cv.z), dv3 = dup2(cv.w);
        #pragma unroll
        for (int p = 0; p < RLN / 2; p++) {
            ulonglong2 x2a = *(const ulonglong2*)&xs2[p][k];
            ulonglong2 x2b = *(const ulonglong2*)&xs2[p][k + 2];
            fma2(aK[p], x2a.x, dk0); fma2(aK[p], x2a.y, dk1);
            fma2(aK[p], x2b.x, dk2); fma2(aK[p], x2b.y, dk3);
            fma2(aV[p], x2a.x, dv0); fma2(aV[p], x2a.y, dv1);
            fma2(aV[p], x2b.x, dv2); fma2(aV[p], x2b.y, dv3);
        }
        ck = nk; cv = nv;
    }
    float bkc = bk[c], bvc = bv[c];
    #pragma unroll
    for (int p = 0; p < RLN / 2; p++) {
        float2 k2 = unpk(aK[p]);
        g_K[(size_t)(row0 + 2 * p) * Dd + c]     = k2.x + bkc;
        g_K[(size_t)(row0 + 2 * p + 1) * Dd + c] = k2.y + bkc;
    }
    #pragma unroll
    for (int q = 0; q < RLN / 4; q++) {
        float2 a = unpk(aV[2 * q]);
        float2 bqv = unpk(aV[2 * q + 1]);
        float4 vq = make_float4(a.x + bvc, a.y + bvc, bqv.x + bvc, bqv.y + bvc);
        g_V4[((size_t)(row0 / 4) + q) * Dd + c] = vq;
    }
}

// ---------------- persistent kernel: all 48 iterations ------------------------
// grid = Bz * 9. roles 0-5: dots tiles (each computes full 21-row Q in smem).
// roles 6-8: slot updates (7 rows each).
union SMem {
    struct { float qs[Ss][Dd]; float Ks[32][68]; float ds[32][24]; } d;  // 33.3KB
    struct { float2 asp[4][Nn]; float2 usp[4][Dd]; float2 hsp[4][Dd];
             float2 fsp[4][Dd]; float inv_[8]; } s;
};

__global__ __launch_bounds__(256, 2)
void persist_kernel(float* __restrict__ out_attn,
                    const float* __restrict__ b_ih, const float* __restrict__ b_hh,
                    const float* __restrict__ g_ff, const float* __restrict__ be_ff,
                    const float* __restrict__ b1, const float* __restrict__ b2,
                    const float* __restrict__ g_sl, const float* __restrict__ be_sl,
                    const float* __restrict__ bq) {
    __shared__ SMem sm;
    int b = blockIdx.x / 9;
    int role = blockIdx.x % 9;
    int t = threadIdx.x, w = t >> 5, l = t & 31;

    if (role < 6) {
        // ================= DOTS block =================
        int j0 = role * 32;
        int jj = l;
        int i0 = w, i1 = w + 8, i2 = w + 16;
        bool has2 = (i2 < Ss);

        for (int iter = 0; iter < NFr * 3; iter++) {
            int f = iter / 3, it = iter - 3 * f;

            // ---- Q-phase: LN(slots) -> qs, then Q = qs @ WqT + bq (in-place)
            wait_ge(&g_slot_done[b], 3u * iter);
            for (int r = w; r < Ss; r += 8) {
                const float* src = g_slots + ((size_t)b * Ss + r) * Dd;
                float v[8]; float s = 0.f;
                #pragma unroll
                for (int u = 0; u < 8; u++) { v[u] = __ldcg(&src[l + 32 * u]); s += v[u]; }
                s = warp_sum(s);
                float m = s * (1.0f / Dd);
                float vs = 0.f;
                #pragma unroll
                for (int u = 0; u < 8; u++) { v[u] -= m; vs += v[u] * v[u]; }
                vs = warp_sum(vs);
                float iv = rsqrtf(vs * (1.0f / Dd) + LN_EPS);
                #pragma unroll
                for (int u = 0; u < 8; u++) {
                    int k = l + 32 * u;
                    sm.d.qs[r][k] = v[u] * iv * g_sl[k] + be_sl[k];
                }
            }
            __syncthreads();
            {
                int c = t;
                float acc[Ss];
                float bqc = bq[c];
                #pragma unroll
                for (int r = 0; r < Ss; r++) acc[r] = bqc;
                const float4* wp = g_WqT4 + c;
                float4 cw = ldcg4(wp);
                for (int kq = 0; kq < 64; kq++) {
                    float4 nw = ldcg4(wp + (size_t)(kq < 63 ? kq + 1 : 63) * Dd);
                    int k = 4 * kq;
                    #pragma unroll
                    for (int r = 0; r < Ss; r++) {
                        float4 x4 = *(const float4*)&sm.d.qs[r][k];
                        acc[r] = fmaf(x4.x, cw.x, acc[r]);
                        acc[r] = fmaf(x4.y, cw.y, acc[r]);
                        acc[r] = fmaf(x4.z, cw.z, acc[r]);
                        acc[r] = fmaf(x4.w, cw.w, acc[r]);
                    }
                    cw = nw;
                }
                __syncthreads();   // all LN reads done before overwrite
                #pragma unroll
                for (int r = 0; r < Ss; r++) sm.d.qs[r][c] = acc[r];
            }
            __syncthreads();

            // ---- dots main (Q resident in smem; stage only K tiles) ----
            u64 A0 = 0ULL, A1 = 0ULL, A2 = 0ULL;
            const float* Kbase = g_K + (((size_t)b * NFr + f) * Nn) * Dd;
            for (int k0 = 0; k0 < Dd; k0 += 64) {
                for (int idx = t; idx < 32 * 16; idx += 256) {
                    int r = idx >> 4, kk4 = (idx & 15) * 4;
                    *(float4*)&sm.d.Ks[r][kk4] =
                        *(const float4*)&Kbase[(size_t)(j0 + r) * Dd + k0 + kk4];
                }
                __syncthreads();
                #pragma unroll
                for (int kk = 0; kk < 64; kk += 4) {
                    ulonglong2 kp = *(const ulonglong2*)&sm.d.Ks[jj][kk];
                    ulonglong2 q0 = *(const ulonglong2*)&sm.d.qs[i0][k0 + kk];
                    ulonglong2 q1 = *(const ulonglong2*)&sm.d.qs[i1][k0 + kk];
                    fma2(A0, kp.x, q0.x); fma2(A0, kp.y, q0.y);
                    fma2(A1, kp.x, q1.x); fma2(A1, kp.y, q1.y);
                    if (has2) {
                        ulonglong2 q2 = *(const ulonglong2*)&sm.d.qs[i2][k0 + kk];
                        fma2(A2, kp.x, q2.x); fma2(A2, kp.y, q2.y);
                    }
                }
                __syncthreads();
            }
            float2 s0 = unpk(A0), s1 = unpk(A1);
            sm.d.ds[jj][i0] = (s0.x + s0.y) * 0.0625f;
            sm.d.ds[jj][i1] = (s1.x + s1.y) * 0.0625f;
            if (has2) { float2 s2 = unpk(A2); sm.d.ds[jj][i2] = (s2.x + s2.y) * 0.0625f; }
            __syncthreads();
            for (int q = w; q < 32; q += 8) {
                float v = (l < Ss) ? sm.d.ds[q][l] : -3.4e38f;
                float mx = warp_max(v);
                float e = (l < Ss) ? expf(v - mx) : 0.f;
                float smv = warp_sum(e);
                if (l < Ss) {
                    float a = e / smv + EPSs;
                    g_At[((size_t)b * Nn + j0 + q) * Ss + l] = a;
                    if (it == 2)
                        out_attn[(((size_t)b * NFr + f) * Ss + l) * Nn + j0 + q] = a;
                }
            }
            __syncthreads();
            signal(&g_dots_done[b]);
        }
    } else {
        // ================= SLOT block =================
        int i0 = (role - 6) * RS;
        int c = t;
        for (int iter = 0; iter < NFr * 3; iter++) {
            int f = iter / 3;

            // ---- EARLY: h0 + h-side GRU gates (overlaps dots+Q) ----
            float h0lo[4], h0hi[4];
            #pragma unroll
            for (int p = 0; p < 4; p++) {
                int rlo = 2 * p, rhi = (2 * p + 1 < RS) ? 2 * p + 1 : RS - 1;
                h0lo[p] = g_slots[((size_t)b * Ss + i0 + rlo) * Dd + c];
                h0hi[p] = g_slots[((size_t)b * Ss + i0 + rhi) * Dd + c];
            }
            #pragma unroll
            for (int p = 0; p < 4; p++) sm.s.hsp[p][c] = make_float2(h0lo[p], h0hi[p]);
            __syncthreads();

            u64 a_hr[4], a_hz[4], a_hn[4];
            #pragma unroll
            for (int p = 0; p < 4; p++) { a_hr[p] = 0ULL; a_hz[p] = 0ULL; a_hn[p] = 0ULL; }
            {
                const float4* wh4 = g_WhhT4 + c;
                float4 cvr = ldcg4(wh4), cvz = ldcg4(wh4 + Dd), cvn = ldcg4(wh4 + 2 * Dd);
                for (int kq = 0; kq < 64; kq++) {
                    size_t nx = (size_t)(kq < 63 ? kq + 1 : 63) * (3 * Dd);
                    float4 nvr = ldcg4(wh4 + nx), nvz = ldcg4(wh4 + nx + Dd),
                           nvn = ldcg4(wh4 + nx + 2 * Dd);
                    int k = 4 * kq;
                    #pragma unroll
                    for (int p = 0; p < 4; p++) {
                        ulonglong2 h2a = *(const ulonglong2*)&sm.s.hsp[p][k];
                        ulonglong2 h2b = *(const ulonglong2*)&sm.s.hsp[p][k + 2];
                        fma2(a_hr[p], h2a.x, dup2(cvr.x)); fma2(a_hr[p], h2a.y, dup2(cvr.y));
                        fma2(a_hr[p], h2b.x, dup2(cvr.z)); fma2(a_hr[p], h2b.y, dup2(cvr.w));
                        fma2(a_hz[p], h2a.x, dup2(cvz.x)); fma2(a_hz[p], h2a.y, dup2(cvz.y));
                        fma2(a_hz[p], h2b.x, dup2(cvz.z)); fma2(a_hz[p], h2b.y, dup2(cvz.w));
                        fma2(a_hn[p], h2a.x, dup2(cvn.x)); fma2(a_hn[p], h2a.y, dup2(cvn.y));
                        fma2(a_hn[p], h2b.x, dup2(cvn.z)); fma2(a_hn[p], h2b.y, dup2(cvn.w));
                    }
                    cvr = nvr; cvz = nvz; cvn = nvn;
                }
            }

            wait_ge(&g_dots_done[b], 6u * (iter + 1));

            // Phase A: stage attn + row sums
            for (int idx = t; idx < 8 * Nn; idx += 256) {
                int lr = idx & 7, j = idx >> 3;
                int row = (lr < 7) ? lr : 6;
                ((float*)sm.s.asp)[((size_t)(lr >> 1) * Nn + j) * 2 + (lr & 1)] =
                    __ldcg(&g_At[((size_t)b * Nn + j) * Ss + i0 + row]);
            }
            __syncthreads();
            {
                int p = w >> 1, e = w & 1;
                float s = 0.f;
                #pragma unroll
                for (int u = 0; u < Nn / 32; u++)
                    s += ((const float*)sm.s.asp)[((size_t)p * Nn + l + 32 * u) * 2 + e];
                s = warp_sum(s);
                if (l == 0) sm.s.inv_[w] = 1.0f / s;
            }
            __syncthreads();

            // Phase B: updates = (A/rowsum) @ V
            u64 accU[4];
            #pragma unroll
            for (int p = 0; p < 4; p++) accU[p] = 0ULL;
            const float4* vp4 = g_V4 + (((size_t)b * NFr + f) * (Nn / 4)) * Dd + c;
            float4 cvv = vp4[0];
            for (int nq = 0; nq < Nn / 4; nq++) {
                float4 nvv = vp4[(size_t)(nq < Nn / 4 - 1 ? nq + 1 : nq) * Dd];
                int j = 4 * nq;
                u64 vd0 = dup2(cvv.x), vd1 = dup2(cvv.y);
                u64 vd2 = dup2(cvv.z), vd3 = dup2(cvv.w);
                #pragma unroll
                for (int p = 0; p < 4; p++) {
                    ulonglong2 a2a = *(const ulonglong2*)&sm.s.asp[p][j];
                    ulonglong2 a2b = *(const ulonglong2*)&sm.s.asp[p][j + 2];
                    fma2(accU[p], a2a.x, vd0); fma2(accU[p], a2a.y, vd1);
                    fma2(accU[p], a2b.x, vd2); fma2(accU[p], a2b.y, vd3);
                }
                cvv = nvv;
            }
            #pragma unroll
            for (int p = 0; p < 4; p++) {
                float2 u2 = unpk(accU[p]);
                sm.s.usp[p][c] = make_float2(u2.x * sm.s.inv_[2 * p],
                                             u2.y * sm.s.inv_[2 * p + 1]);
            }
            __syncthreads();

            // Phase C: u-side GRU gates
            u64 a_ir[4], a_iz[4], a_in[4];
            #pragma unroll
            for (int p = 0; p < 4; p++) { a_ir[p] = 0ULL; a_iz[p] = 0ULL; a_in[p] = 0ULL; }
            {
                const float4* wi4 = g_WihT4 + c;
                float4 cwr = ldcg4(wi4), cwz = ldcg4(wi4 + Dd), cwn = ldcg4(wi4 + 2 * Dd);
                for (int kq = 0; kq < 64; kq++) {
                    size_t nx = (size_t)(kq < 63 ? kq + 1 : 63) * (3 * Dd);
                    float4 nwr = ldcg4(wi4 + nx), nwz = ldcg4(wi4 + nx + Dd),
                           nwn = ldcg4(wi4 + nx + 2 * Dd);
                    int k = 4 * kq;
                    #pragma unroll
                    for (int p = 0; p < 4; p++) {
                        ulonglong2 u2a = *(const ulonglong2*)&sm.s.usp[p][k];
                        ulonglong2 u2b = *(const ulonglong2*)&sm.s.usp[p][k + 2];
                        fma2(a_ir[p], u2a.x, dup2(cwr.x)); fma2(a_ir[p], u2a.y, dup2(cwr.y));
                        fma2(a_ir[p], u2b.x, dup2(cwr.z)); fma2(a_ir[p], u2b.y, dup2(cwr.w));
                        fma2(a_iz[p], u2a.x, dup2(cwz.x)); fma2(a_iz[p], u2a.y, dup2(cwz.y));
                        fma2(a_iz[p], u2b.x, dup2(cwz.z)); fma2(a_iz[p], u2b.y, dup2(cwz.w));
                        fma2(a_in[p], u2a.x, dup2(cwn.x)); fma2(a_in[p], u2a.y, dup2(cwn.y));
                        fma2(a_in[p], u2b.x, dup2(cwn.z)); fma2(a_in[p], u2b.y, dup2(cwn.w));
                    }
                    cwr = nwr; cwz = nwz; cwn = nwn;
                }
            }
            float bir = b_ih[c], biz = b_ih[Dd + c], bin = b_ih[2 * Dd + c];
            float bhr = b_hh[c], bhz = b_hh[Dd + c], bhn = b_hh[2 * Dd + c];
            float hnlo[4], hnhi[4];
            #pragma unroll
            for (int p = 0; p < 4; p++) {
                float2 ir2 = unpk(a_ir[p]), iz2 = unpk(a_iz[p]), in2 = unpk(a_in[p]);
                float2 hr2 = unpk(a_hr[p]), hz2 = unpk(a_hz[p]), hn2 = unpk(a_hn[p]);
                {
                    float rg = 1.f / (1.f + expf(-(ir2.x + bir + hr2.x + bhr)));
                    float zg = 1.f / (1.f + expf(-(iz2.x + biz + hz2.x + bhz)));
                    float ng = tanhf(in2.x + bin + rg * (hn2.x + bhn));
                    hnlo[p] = (1.f - zg) * ng + zg * h0lo[p];
                }
                {
                    float rg = 1.f / (1.f + expf(-(ir2.y + bir + hr2.y + bhr)));
                    float zg = 1.f / (1.f + expf(-(iz2.y + biz + hz2.y + bhz)));
                    float ng = tanhf(in2.y + bin + rg * (hn2.y + bhn));
                    hnhi[p] = (1.f - zg) * ng + zg * h0hi[p];
                }
            }
            __syncthreads();
            #pragma unroll
            for (int p = 0; p < 4; p++) sm.s.usp[p][c] = make_float2(hnlo[p], hnhi[p]);
            __syncthreads();

            // Phase D: LN(hnew; g_ff) -> hsp
            {
                int p = w >> 1, e = w & 1;
                float v[8]; float s = 0.f;
                #pragma unroll
                for (int u = 0; u < 8; u++) {
                    v[u] = ((const float*)sm.s.usp)[((size_t)p * Dd + l + 32 * u) * 2 + e];
                    s += v[u];
                }
                s = warp_sum(s);
                float m = s * (1.0f / Dd);
                float vs = 0.f;
                #pragma unroll
                for (int u = 0; u < 8; u++) { v[u] -= m; vs += v[u] * v[u]; }
                vs = warp_sum(vs);
                float iv = rsqrtf(vs * (1.0f / Dd) + LN_EPS);
                #pragma unroll
                for (int u = 0; u < 8; u++) {
                    int k = l + 32 * u;
                    ((float*)sm.s.hsp)[((size_t)p * Dd + k) * 2 + e] =
                        v[u] * iv * g_ff[k] + be_ff[k];
                }
            }
            __syncthreads();

            // Phase E: FF = relu(LN @ W1T + b1) -> fsp
            {
                u64 aF[4];
                #pragma unroll
                for (int p = 0; p < 4; p++) aF[p] = 0ULL;
                const float4* wp = g_W1T4 + c;
                float4 cw = ldcg4(wp);
                for (int kq = 0; kq < 64; kq++) {
                    float4 nw = ldcg4(wp + (size_t)(kq < 63 ? kq + 1 : 63) * Dd);
                    int k = 4 * kq;
                    u64 d0 = dup2(cw.x), d1 = dup2(cw.y), d2 = dup2(cw.z), d3 = dup2(cw.w);
                    #pragma unroll
                    for (int p = 0; p < 4; p++) {
                        ulonglong2 x2a = *(const ulonglong2*)&sm.s.hsp[p][k];
                        ulonglong2 x2b = *(const ulonglong2*)&sm.s.hsp[p][k + 2];
                        fma2(aF[p], x2a.x, d0); fma2(aF[p], x2a.y, d1);
                        fma2(aF[p], x2b.x, d2); fma2(aF[p], x2b.y, d3);
                    }
                    cw = nw;
                }
                float b1c = b1[c];
                #pragma unroll
                for (int p = 0; p < 4; p++) {
                    float2 f2 = unpk(aF[p]);
                    sm.s.fsp[p][c] = make_float2(fmaxf(f2.x + b1c, 0.f),
                                                 fmaxf(f2.y + b1c, 0.f));
                }
            }
            __syncthreads();

            // Phase F: slots_new = hnew + fsp @ W2T + b2 -> global; then signal
            {
                u64 aO[4];
                #pragma unroll
                for (int p = 0; p < 4; p++) aO[p] = 0ULL;
                const float4* wp = g_W2T4 + c;
                float4 cw = ldcg4(wp);
                for (int kq = 0; kq < 64; kq++) {
                    float4 nw = ldcg4(wp + (size_t)(kq < 63 ? kq + 1 : 63) * Dd);
                    int k = 4 * kq;
                    u64 d0 = dup2(cw.x), d1 = dup2(cw.y), d2 = dup2(cw.z), d3 = dup2(cw.w);
                    #pragma unroll
                    for (int p = 0; p < 4; p++) {
                        ulonglong2 x2a = *(const ulonglong2*)&sm.s.fsp[p][k];
                        ulonglong2 x2b = *(const ulonglong2*)&sm.s.fsp[p][k + 2];
                        fma2(aO[p], x2a.x, d0); fma2(aO[p], x2a.y, d1);
                        fma2(aO[p], x2b.x, d2); fma2(aO[p], x2b.y, d3);
                    }
                    cw = nw;
                }
                float b2c = b2[c];
                #pragma unroll
                for (int p = 0; p < 4; p++) {
                    float2 o2 = unpk(aO[p]);
                    float snlo = hnlo[p] + o2.x + b2c;
                    float snhi = hnhi[p] + o2.y + b2c;
                    int rlo = i0 + 2 * p;
                    g_slots[((size_t)b * Ss + rlo) * Dd + c] = snlo;
                    if (2 * p + 1 < RS) g_slots[((size_t)b * Ss + rlo + 1) * Dd + c] = snhi;
                }
            }
            signal(&g_slot_done[b]);
        }
    }
}

// ---------------- output slots ------------------------------------------------
__global__ void out_slots_kernel(float* __restrict__ out) {
    int idx = blockIdx.x * blockDim.x + threadIdx.x;
    int d = idx & (Dd - 1);
    int rest = idx / Dd;
    int s = rest % NA;
    int b = rest / NA;
    out[idx] = g_slots[((size_t)b * Ss + s) * Dd + d];
}

// ---------------- launch ------------------------------------------------------
extern "C" void kernel_launch(void* const* d_in, const int* in_sizes, int n_in,
                              void* d_out, int out_size) {
    const float* inputs = (const float*)d_in[0];
    const float* noise  = (const float*)d_in[1];
    const float* mu     = (const float*)d_in[2];
    const float* sigma  = (const float*)d_in[3];
    const float* Wq     = (const float*)d_in[4];
    const float* bq     = (const float*)d_in[5];
    const float* Wk     = (const float*)d_in[6];
    const float* bk     = (const float*)d_in[7];
    const float* Wv     = (const float*)d_in[8];
    const float* bv     = (const float*)d_in[9];
    const float* W1     = (const float*)d_in[10];
    const float* b1     = (const float*)d_in[11];
    const float* W2     = (const float*)d_in[12];
    const float* b2     = (const float*)d_in[13];
    const float* W_ih   = (const float*)d_in[14];
    const float* b_ih   = (const float*)d_in[15];
    const float* W_hh   = (const float*)d_in[16];
    const float* b_hh   = (const float*)d_in[17];
    const float* gin    = (const float*)d_in[18];
    const float* bein   = (const float*)d_in[19];
    const float* gsl    = (const float*)d_in[20];
    const float* besl   = (const float*)d_in[21];
    const float* gff    = (const float*)d_in[22];
    const float* beff   = (const float*)d_in[23];

    float* out = (float*)d_out;
    float* out_attn = out + (size_t)Bz * NA * Dd;

    setup_kernel<<<344, dim3(32, 8)>>>(Wq, Wk, Wv, W1, W2, W_ih, W_hh,
                                       noise, mu, sigma);
    kv_all_kernel<<<(Bz * NFr * Nn) / RLN, 256>>>(inputs, gin, bein, bk, bv);
    persist_kernel<<<Bz * 9, 256>>>(out_attn, b_ih, b_hh, gff, beff,
                                    b1, b2, gsl, besl, bq);
    out_slots_kernel<<<(Bz * NA * Dd) / 256, 256>>>(out);
}

// round 14
// speedup vs baseline: 1.1057x; 1.1057x over previous
#include <cuda_runtime.h>
#include <math.h>

#define Bz 32
#define NFr 16
#define Dd 256
#define Ss 21
#define Nn 192
#define NA 20
#define EPSs 1e-8f
#define LN_EPS 1e-5f
#define RLN 24
#define RS 7

typedef unsigned long long u64;

// ---------------- packed f32x2 helpers ---------------------------------------
__device__ __forceinline__ void fma2(u64& d, u64 a, u64 b) {
    asm("fma.rn.f32x2 %0, %1, %2, %0;" : "+l"(d) : "l"(a), "l"(b));
}
__device__ __forceinline__ u64 dup2(float v) {
    u64 r; asm("mov.b64 %0, {%1, %1};" : "=l"(r) : "f"(v)); return r;
}
__device__ __forceinline__ float2 unpk(u64 v) {
    float lo, hi; asm("mov.b64 {%0, %1}, %2;" : "=f"(lo), "=f"(hi) : "l"(v));
    return make_float2(lo, hi);
}

// ---------------- scratch ----------------------------------------------------
__device__ float g_K[(size_t)Bz * NFr * Nn * Dd];
__device__ float4 g_V4[(size_t)Bz * NFr * (Nn / 4) * Dd];
__device__ float g_slots[Bz * Ss * Dd];
__device__ float g_Q[Bz * Ss * Dd];
__device__ float g_At[Bz * Nn * Ss];
__device__ unsigned g_dots_done[Bz];
__device__ unsigned g_slot_done[Bz];
__device__ unsigned g_q_done[Bz];
__device__ float4 g_WqT4[64 * Dd];
__device__ float4 g_WkT4[64 * Dd];
__device__ float4 g_WvT4[64 * Dd];
__device__ float4 g_W1T4[64 * Dd];
__device__ float4 g_W2T4[64 * Dd];
__device__ float4 g_WihT4[64 * 3 * Dd];
__device__ float4 g_WhhT4[64 * 3 * Dd];

__device__ __forceinline__ float4 ldcg4(const float4* p) { return __ldcg(p); }

// ---------------- sync helpers ------------------------------------------------
__device__ __forceinline__ void wait_ge(unsigned* p, unsigned tgt) {
    if (threadIdx.x == 0) {
        unsigned v;
        do {
            asm volatile("ld.acquire.gpu.global.u32 %0, [%1];"
                         : "=r"(v) : "l"(p) : "memory");
        } while (v < tgt);
    }
    __syncthreads();
}
__device__ __forceinline__ void signal(unsigned* p) {
    __syncthreads();
    if (threadIdx.x == 0) { __threadfence(); atomicAdd(p, 1u); }
}

// -------- setup: f4-transpose all weights + init slots + zero counters --------
__global__ void setup_kernel(const float* __restrict__ Wq, const float* __restrict__ Wk,
                             const float* __restrict__ Wv, const float* __restrict__ W1,
                             const float* __restrict__ W2, const float* __restrict__ Wih,
                             const float* __restrict__ Whh,
                             const float* __restrict__ noise,
                             const float* __restrict__ mu,
                             const float* __restrict__ sigma) {
    int bid = blockIdx.x;
    int tx = threadIdx.x, ty = threadIdx.y;
    if (bid < 176) {
        __shared__ float4 tile[32][33];
        const float4* src; float4* dst; int R; int tloc;
        if (bid < 80) {
            int m = bid / 16; tloc = bid % 16; R = 256;
            switch (m) {
                case 0: src = (const float4*)Wq; dst = g_WqT4; break;
                case 1: src = (const float4*)Wk; dst = g_WkT4; break;
                case 2: src = (const float4*)Wv; dst = g_WvT4; break;
                case 3: src = (const float4*)W1; dst = g_W1T4; break;
                default: src = (const float4*)W2; dst = g_W2T4; break;
            }
        } else {
            int m = (bid - 80) / 48; tloc = (bid - 80) % 48; R = 768;
            src = (const float4*)(m == 0 ? Wih : Whh);
            dst = (m == 0 ? g_WihT4 : g_WhhT4);
        }
        int bx = (tloc & 1) * 32;
        int by = (tloc >> 1) * 32;
        #pragma unroll
        for (int i = 0; i < 32; i += 8)
            tile[ty + i][tx] = src[(size_t)(by + ty + i) * 64 + bx + tx];
        __syncthreads();
        #pragma unroll
        for (int i = 0; i < 32; i += 8)
            dst[(size_t)(bx + ty + i) * R + by + tx] = tile[tx][ty + i];
    } else {
        int t = ty * 32 + tx;
        int base = (bid - 176) * 1024 + t;
        #pragma unroll
        for (int u = 0; u < 4; u++) {
            int idx = base + u * 256;
            int d = idx & (Dd - 1);
            g_slots[idx] = mu[d] + sigma[d] * noise[idx];
        }
        if (bid == 176 && t < Bz) {
            g_dots_done[t] = 0u; g_slot_done[t] = 0u; g_q_done[t] = 0u;
        }
    }
}

// ---------------- warp helpers ------------------------------------------------
__device__ __forceinline__ float warp_sum(float v) {
    #pragma unroll
    for (int o = 16; o > 0; o >>= 1) v += __shfl_xor_sync(0xffffffffu, v, o);
    return v;
}
__device__ __forceinline__ float warp_max(float v) {
    #pragma unroll
    for (int o = 16; o > 0; o >>= 1) v = fmaxf(v, __shfl_xor_sync(0xffffffffu, v, o));
    return v;
}

// ------- LN(all frames) -> K, V4.  grid = B*NF*N/RLN = 4096 ------------------
__global__ __launch_bounds__(256)
void kv_all_kernel(const float* __restrict__ inputs,
                   const float* __restrict__ gam, const float* __restrict__ bet,
                   const float* __restrict__ bk, const float* __restrict__ bv) {
    __shared__ float2 xs2[RLN / 2][Dd];
    int row0 = blockIdx.x * RLN;
    int t = threadIdx.x, w = t >> 5, l = t & 31;

    for (int rr = w; rr < RLN; rr += 8) {
        int row = row0 + rr;
        const float* src = inputs + (size_t)row * Dd;
        float v[8]; float s = 0.f;
        #pragma unroll
        for (int u = 0; u < 8; u++) { v[u] = src[l + 32 * u]; s += v[u]; }
        s = warp_sum(s);
        float m = s * (1.0f / Dd);
        float vs = 0.f;
        #pragma unroll
        for (int u = 0; u < 8; u++) { v[u] -= m; vs += v[u] * v[u]; }
        vs = warp_sum(vs);
        float inv = rsqrtf(vs * (1.0f / Dd) + LN_EPS);
        int p = rr >> 1, e = rr & 1;
        #pragma unroll
        for (int u = 0; u < 8; u++) {
            int k = l + 32 * u;
            ((float*)xs2)[((size_t)p * Dd + k) * 2 + e] = v[u] * inv * gam[k] + bet[k];
        }
    }
    __syncthreads();

    int c = t;
    u64 aK[RLN / 2], aV[RLN / 2];
    #pragma unroll
    for (int p = 0; p < RLN / 2; p++) { aK[p] = 0ULL; aV[p] = 0ULL; }
    const float4* wk4 = g_WkT4 + c;
    const float4* wv4 = g_WvT4 + c;
    float4 ck = wk4[0], cv = wv4[0];
    for (int kq = 0; kq < 64; kq++) {
        int nx = (kq < 63 ? kq + 1 : 63) * Dd;
        float4 nk = wk4[nx], nv = wv4[nx];
        int k = 4 * kq;
        u64 dk0 = dup2(ck.x), dk1 = dup2(ck.y), dk2 = dup2(ck.z), dk3 = dup2(ck.w);
        u64 dv0 = dup2(cv.x), dv1 = dup2(cv.y), dv2 = dup2(cv.z), dv3 = dup2(cv.w);
        #pragma unroll
        for (int p = 0; p < RLN / 2; p++) {
            ulonglong2 x2a = *(const ulonglong2*)&xs2[p][k];
            ulonglong2 x2b = *(const ulonglong2*)&xs2[p][k + 2];
            fma2(aK[p], x2a.x, dk0); fma2(aK[p], x2a.y, dk1);
            fma2(aK[p], x2b.x, dk2); fma2(aK[p], x2b.y, dk3);
            fma2(aV[p], x2a.x, dv0); fma2(aV[p], x2a.y, dv1);
            fma2(aV[p], x2b.x, dv2); fma2(aV[p], x2b.y, dv3);
        }
        ck = nk; cv = nv;
    }
    float bkc = bk[c], bvc = bv[c];
    #pragma unroll
    for (int p = 0; p < RLN / 2; p++) {
        float2 k2 = unpk(aK[p]);
        g_K[(size_t)(row0 + 2 * p) * Dd + c]     = k2.x + bkc;
        g_K[(size_t)(row0 + 2 * p + 1) * Dd + c] = k2.y + bkc;
    }
    #pragma unroll
    for (int q = 0; q < RLN / 4; q++) {
        float2 a = unpk(aV[2 * q]);
        float2 bqv = unpk(aV[2 * q + 1]);
        float4 vq = make_float4(a.x + bvc, a.y + bvc, bqv.x + bvc, bqv.y + bvc);
        g_V4[((size_t)(row0 / 4) + q) * Dd + c] = vq;
    }
}

// ---------------- persistent kernel: all 48 iterations ------------------------
// grid = Bz * 9. roles 0-5: dots (32 j + distributed Q rows, iter 0 included).
// roles 6-8: slot updates (7 rows each; final iter also writes d_out slots).
union SMem {
    struct { float Ks[32][68]; float Qs[Ss][64]; float ds[32][24]; float xq[4][Dd]; } d;
    struct { float2 asp[4][Nn]; float2 usp[4][Dd]; float2 hsp[4][Dd];
             float2 fsp[4][Dd]; float inv_[8]; } s;
};

__global__ __launch_bounds__(256, 2)
void persist_kernel(float* __restrict__ out_slots, float* __restrict__ out_attn,
                    const float* __restrict__ b_ih, const float* __restrict__ b_hh,
                    const float* __restrict__ g_ff, const float* __restrict__ be_ff,
                    const float* __restrict__ b1, const float* __restrict__ b2,
                    const float* __restrict__ g_sl, const float* __restrict__ be_sl,
                    const float* __restrict__ bq) {
    __shared__ SMem sm;
    int b = blockIdx.x / 9;
    int role = blockIdx.x % 9;
    int t = threadIdx.x, w = t >> 5, l = t & 31;

    if (role < 6) {
        // ================= DOTS block =================
        int j0 = role * 32;
        int jj = l;
        int i0 = w, i1 = w + 8, i2 = w + 16;
        bool has2 = (i2 < Ss);
        // Q-row assignment: roles 0-2 -> 4 rows, roles 3-5 -> 3 rows
        int nr  = (role < 3) ? 4 : 3;
        int qs0 = (role < 3) ? role * 4 : 12 + (role - 3) * 3;

        for (int iter = 0; iter < NFr * 3; iter++) {
            int f = iter / 3, it = iter - 3 * f;

            // ---- Q-phase (every iter; iter 0 reads slots0) ----
            {
                wait_ge(&g_slot_done[b], 3u * iter);
                if (w < nr) {
                    int row = qs0 + w;
                    const float* src = g_slots + ((size_t)b * Ss + row) * Dd;
                    float v[8]; float s = 0.f;
                    #pragma unroll
                    for (int u = 0; u < 8; u++) { v[u] = __ldcg(&src[l + 32 * u]); s += v[u]; }
                    s = warp_sum(s);
                    float m = s * (1.0f / Dd);
                    float vs = 0.f;
                    #pragma unroll
                    for (int u = 0; u < 8; u++) { v[u] -= m; vs += v[u] * v[u]; }
                    vs = warp_sum(vs);
                    float iv = rsqrtf(vs * (1.0f / Dd) + LN_EPS);
                    #pragma unroll
                    for (int u = 0; u < 8; u++) {
                        int k = l + 32 * u;
                        sm.d.xq[w][k] = v[u] * iv * g_sl[k] + be_sl[k];
                    }
                }
                if (nr < 4 && w == 4) {  // zero pad row 3
                    #pragma unroll
                    for (int u = 0; u < 8; u++) sm.d.xq[3][l + 32 * u] = 0.f;
                }
                __syncthreads();
                {
                    int c = t;
                    float acc[4];
                    float bqc = bq[c];
                    #pragma unroll
                    for (int r = 0; r < 4; r++) acc[r] = bqc;
                    const float4* wp = g_WqT4 + c;
                    float4 cw = ldcg4(wp);
                    for (int kq = 0; kq < 64; kq++) {
                        float4 nw = ldcg4(wp + (size_t)(kq < 63 ? kq + 1 : 63) * Dd);
                        int k = 4 * kq;
                        #pragma unroll
                        for (int r = 0; r < 4; r++) {
                            float4 x4 = *(const float4*)&sm.d.xq[r][k];
                            acc[r] = fmaf(x4.x, cw.x, acc[r]);
                            acc[r] = fmaf(x4.y, cw.y, acc[r]);
                            acc[r] = fmaf(x4.z, cw.z, acc[r]);
                            acc[r] = fmaf(x4.w, cw.w, acc[r]);
                        }
                        cw = nw;
                    }
                    for (int r = 0; r < nr; r++)
                        g_Q[((size_t)b * Ss + qs0 + r) * Dd + c] = acc[r];
                }
                signal(&g_q_done[b]);
                wait_ge(&g_q_done[b], 6u * (iter + 1));
            }

            // ---- dots main ----
            u64 A0 = 0ULL, A1 = 0ULL, A2 = 0ULL;
            const float* Kbase = g_K + (((size_t)b * NFr + f) * Nn) * Dd;
            for (int k0 = 0; k0 < Dd; k0 += 64) {
                for (int idx = t; idx < 32 * 16; idx += 256) {
                    int r = idx >> 4, kk4 = (idx & 15) * 4;
                    *(float4*)&sm.d.Ks[r][kk4] =
                        *(const float4*)&Kbase[(size_t)(j0 + r) * Dd + k0 + kk4];
                }
                for (int idx = t; idx < Ss * 16; idx += 256) {
                    int r = idx >> 4, kk4 = (idx & 15) * 4;
                    *(float4*)&sm.d.Qs[r][kk4] =
                        __ldcg((const float4*)&g_Q[((size_t)b * Ss + r) * Dd + k0 + kk4]);
                }
                __syncthreads();
                #pragma unroll
                for (int kk = 0; kk < 64; kk += 4) {
                    ulonglong2 kp = *(const ulonglong2*)&sm.d.Ks[jj][kk];
                    ulonglong2 q0 = *(const ulonglong2*)&sm.d.Qs[i0][kk];
                    ulonglong2 q1 = *(const ulonglong2*)&sm.d.Qs[i1][kk];
                    fma2(A0, kp.x, q0.x); fma2(A0, kp.y, q0.y);
                    fma2(A1, kp.x, q1.x); fma2(A1, kp.y, q1.y);
                    if (has2) {
                        ulonglong2 q2 = *(const ulonglong2*)&sm.d.Qs[i2][kk];
                        fma2(A2, kp.x, q2.x); fma2(A2, kp.y, q2.y);
                    }
                }
                __syncthreads();
            }
            float2 s0 = unpk(A0), s1 = unpk(A1);
            sm.d.ds[jj][i0] = (s0.x + s0.y) * 0.0625f;
            sm.d.ds[jj][i1] = (s1.x + s1.y) * 0.0625f;
            if (has2) { float2 s2 = unpk(A2); sm.d.ds[jj][i2] = (s2.x + s2.y) * 0.0625f; }
            __syncthreads();
            for (int q = w; q < 32; q += 8) {
                float v = (l < Ss) ? sm.d.ds[q][l] : -3.4e38f;
                float mx = warp_max(v);
                float e = (l < Ss) ? expf(v - mx) : 0.f;
                float smv = warp_sum(e);
                if (l < Ss) {
                    float a = e / smv + EPSs;
                    g_At[((size_t)b * Nn + j0 + q) * Ss + l] = a;
                    if (it == 2)
                        out_attn[(((size_t)b * NFr + f) * Ss + l) * Nn + j0 + q] = a;
                }
            }
            __syncthreads();
            signal(&g_dots_done[b]);
        }
    } else {
        // ================= SLOT block =================
        int i0 = (role - 6) * RS;
        int c = t;
        for (int iter = 0; iter < NFr * 3; iter++) {
            int f = iter / 3;

            // ---- EARLY: h0 + h-side GRU gates (overlaps dots+Q) ----
            float h0lo[4], h0hi[4];
            #pragma unroll
            for (int p = 0; p < 4; p++) {
                int rlo = 2 * p, rhi = (2 * p + 1 < RS) ? 2 * p + 1 : RS - 1;
                h0lo[p] = g_slots[((size_t)b * Ss + i0 + rlo) * Dd + c];
                h0hi[p] = g_slots[((size_t)b * Ss + i0 + rhi) * Dd + c];
            }
            #pragma unroll
            for (int p = 0; p < 4; p++) sm.s.hsp[p][c] = make_float2(h0lo[p], h0hi[p]);
            __syncthreads();

            u64 a_hr[4], a_hz[4], a_hn[4];
            #pragma unroll
            for (int p = 0; p < 4; p++) { a_hr[p] = 0ULL; a_hz[p] = 0ULL; a_hn[p] = 0ULL; }
            {
                const float4* wh4 = g_WhhT4 + c;
                float4 cvr = ldcg4(wh4), cvz = ldcg4(wh4 + Dd), cvn = ldcg4(wh4 + 2 * Dd);
                for (int kq = 0; kq < 64; kq++) {
                    size_t nx = (size_t)(kq < 63 ? kq + 1 : 63) * (3 * Dd);
                    float4 nvr = ldcg4(wh4 + nx), nvz = ldcg4(wh4 + nx + Dd),
                           nvn = ldcg4(wh4 + nx + 2 * Dd);
                    int k = 4 * kq;
                    #pragma unroll
                    for (int p = 0; p < 4; p++) {
                        ulonglong2 h2a = *(const ulonglong2*)&sm.s.hsp[p][k];
                        ulonglong2 h2b = *(const ulonglong2*)&sm.s.hsp[p][k + 2];
                        fma2(a_hr[p], h2a.x, dup2(cvr.x)); fma2(a_hr[p], h2a.y, dup2(cvr.y));
                        fma2(a_hr[p], h2b.x, dup2(cvr.z)); fma2(a_hr[p], h2b.y, dup2(cvr.w));
                        fma2(a_hz[p], h2a.x, dup2(cvz.x)); fma2(a_hz[p], h2a.y, dup2(cvz.y));
                        fma2(a_hz[p], h2b.x, dup2(cvz.z)); fma2(a_hz[p], h2b.y, dup2(cvz.w));
                        fma2(a_hn[p], h2a.x, dup2(cvn.x)); fma2(a_hn[p], h2a.y, dup2(cvn.y));
                        fma2(a_hn[p], h2b.x, dup2(cvn.z)); fma2(a_hn[p], h2b.y, dup2(cvn.w));
                    }
                    cvr = nvr; cvz = nvz; cvn = nvn;
                }
            }

            wait_ge(&g_dots_done[b], 6u * (iter + 1));

            // Phase A: stage attn + row sums
            for (int idx = t; idx < 8 * Nn; idx += 256) {
                int lr = idx & 7, j = idx >> 3;
                int row = (lr < 7) ? lr : 6;
                ((float*)sm.s.asp)[((size_t)(lr >> 1) * Nn + j) * 2 + (lr & 1)] =
                    __ldcg(&g_At[((size_t)b * Nn + j) * Ss + i0 + row]);
            }
            __syncthreads();
            {
                int p = w >> 1, e = w & 1;
                float s = 0.f;
                #pragma unroll
                for (int u = 0; u < Nn / 32; u++)
                    s += ((const float*)sm.s.asp)[((size_t)p * Nn + l + 32 * u) * 2 + e];
                s = warp_sum(s);
                if (l == 0) sm.s.inv_[w] = 1.0f / s;
            }
            __syncthreads();

            // Phase B: updates = (A/rowsum) @ V
            u64 accU[4];
            #pragma unroll
            for (int p = 0; p < 4; p++) accU[p] = 0ULL;
            const float4* vp4 = g_V4 + (((size_t)b * NFr + f) * (Nn / 4)) * Dd + c;
            float4 cvv = vp4[0];
            for (int nq = 0; nq < Nn / 4; nq++) {
                float4 nvv = vp4[(size_t)(nq < Nn / 4 - 1 ? nq + 1 : nq) * Dd];
                int j = 4 * nq;
                u64 vd0 = dup2(cvv.x), vd1 = dup2(cvv.y);
                u64 vd2 = dup2(cvv.z), vd3 = dup2(cvv.w);
                #pragma unroll
                for (int p = 0; p < 4; p++) {
                    ulonglong2 a2a = *(const ulonglong2*)&sm.s.asp[p][j];
                    ulonglong2 a2b = *(const ulonglong2*)&sm.s.asp[p][j + 2];
                    fma2(accU[p], a2a.x, vd0); fma2(accU[p], a2a.y, vd1);
                    fma2(accU[p], a2b.x, vd2); fma2(accU[p], a2b.y, vd3);
                }
                cvv = nvv;
            }
            #pragma unroll
            for (int p = 0; p < 4; p++) {
                float2 u2 = unpk(accU[p]);
                sm.s.usp[p][c] = make_float2(u2.x * sm.s.inv_[2 * p],
                                             u2.y * sm.s.inv_[2 * p + 1]);
            }
            __syncthreads();

            // Phase C: u-side GRU gates
            u64 a_ir[4], a_iz[4], a_in[4];
            #pragma unroll
            for (int p = 0; p < 4; p++) { a_ir[p] = 0ULL; a_iz[p] = 0ULL; a_in[p] = 0ULL; }
            {
                const float4* wi4 = g_WihT4 + c;
                float4 cwr = ldcg4(wi4), cwz = ldcg4(wi4 + Dd), cwn = ldcg4(wi4 + 2 * Dd);
                for (int kq = 0; kq < 64; kq++) {
                    size_t nx = (size_t)(kq < 63 ? kq + 1 : 63) * (3 * Dd);
                    float4 nwr = ldcg4(wi4 + nx), nwz = ldcg4(wi4 + nx + Dd),
                           nwn = ldcg4(wi4 + nx + 2 * Dd);
                    int k = 4 * kq;
                    #pragma unroll
                    for (int p = 0; p < 4; p++) {
                        ulonglong2 u2a = *(const ulonglong2*)&sm.s.usp[p][k];
                        ulonglong2 u2b = *(const ulonglong2*)&sm.s.usp[p][k + 2];
                        fma2(a_ir[p], u2a.x, dup2(cwr.x)); fma2(a_ir[p], u2a.y, dup2(cwr.y));
                        fma2(a_ir[p], u2b.x, dup2(cwr.z)); fma2(a_ir[p], u2b.y, dup2(cwr.w));
                        fma2(a_iz[p], u2a.x, dup2(cwz.x)); fma2(a_iz[p], u2a.y, dup2(cwz.y));
                        fma2(a_iz[p], u2b.x, dup2(cwz.z)); fma2(a_iz[p], u2b.y, dup2(cwz.w));
                        fma2(a_in[p], u2a.x, dup2(cwn.x)); fma2(a_in[p], u2a.y, dup2(cwn.y));
                        fma2(a_in[p], u2b.x, dup2(cwn.z)); fma2(a_in[p], u2b.y, dup2(cwn.w));
                    }
                    cwr = nwr; cwz = nwz; cwn = nwn;
                }
            }
            float bir = b_ih[c], biz = b_ih[Dd + c], bin = b_ih[2 * Dd + c];
            float bhr = b_hh[c], bhz = b_hh[Dd + c], bhn = b_hh[2 * Dd + c];
            float hnlo[4], hnhi[4];
            #pragma unroll
            for (int p = 0; p < 4; p++) {
                float2 ir2 = unpk(a_ir[p]), iz2 = unpk(a_iz[p]), in2 = unpk(a_in[p]);
                float2 hr2 = unpk(a_hr[p]), hz2 = unpk(a_hz[p]), hn2 = unpk(a_hn[p]);
                {
                    float rg = 1.f / (1.f + expf(-(ir2.x + bir + hr2.x + bhr)));
                    float zg = 1.f / (1.f + expf(-(iz2.x + biz + hz2.x + bhz)));
                    float ng = tanhf(in2.x + bin + rg * (hn2.x + bhn));
                    hnlo[p] = (1.f - zg) * ng + zg * h0lo[p];
                }
                {
                    float rg = 1.f / (1.f + expf(-(ir2.y + bir + hr2.y + bhr)));
                    float zg = 1.f / (1.f + expf(-(iz2.y + biz + hz2.y + bhz)));
                    float ng = tanhf(in2.y + bin + rg * (hn2.y + bhn));
                    hnhi[p] = (1.f - zg) * ng + zg * h0hi[p];
                }
            }
            __syncthreads();
            #pragma unroll
            for (int p = 0; p < 4; p++) sm.s.usp[p][c] = make_float2(hnlo[p], hnhi[p]);
            __syncthreads();

            // Phase D: LN(hnew; g_ff) -> hsp
            {
                int p = w >> 1, e = w & 1;
                float v[8]; float s = 0.f;
                #pragma unroll
                for (int u = 0; u < 8; u++) {
                    v[u] = ((const float*)sm.s.usp)[((size_t)p * Dd + l + 32 * u) * 2 + e];
                    s += v[u];
                }
                s = warp_sum(s);
                float m = s * (1.0f / Dd);
                float vs = 0.f;
                #pragma unroll
                for (int u = 0; u < 8; u++) { v[u] -= m; vs += v[u] * v[u]; }
                vs = warp_sum(vs);
                float iv = rsqrtf(vs * (1.0f / Dd) + LN_EPS);
                #pragma unroll
                for (int u = 0; u < 8; u++) {
                    int k = l + 32 * u;
                    ((float*)sm.s.hsp)[((size_t)p * Dd + k) * 2 + e] =
                        v[u] * iv * g_ff[k] + be_ff[k];
                }
            }
            __syncthreads();

            // Phase E: FF = relu(LN @ W1T + b1) -> fsp
            {
                u64 aF[4];
                #pragma unroll
                for (int p = 0; p < 4; p++) aF[p] = 0ULL;
                const float4* wp = g_W1T4 + c;
                float4 cw = ldcg4(wp);
                for (int kq = 0; kq < 64; kq++) {
                    float4 nw = ldcg4(wp + (size_t)(kq < 63 ? kq + 1 : 63) * Dd);
                    int k = 4 * kq;
                    u64 d0 = dup2(cw.x), d1 = dup2(cw.y), d2 = dup2(cw.z), d3 = dup2(cw.w);
                    #pragma unroll
                    for (int p = 0; p < 4; p++) {
                        ulonglong2 x2a = *(const ulonglong2*)&sm.s.hsp[p][k];
                        ulonglong2 x2b = *(const ulonglong2*)&sm.s.hsp[p][k + 2];
                        fma2(aF[p], x2a.x, d0); fma2(aF[p], x2a.y, d1);
                        fma2(aF[p], x2b.x, d2); fma2(aF[p], x2b.y, d3);
                    }
                    cw = nw;
                }
                float b1c = b1[c];
                #pragma unroll
                for (int p = 0; p < 4; p++) {
                    float2 f2 = unpk(aF[p]);
                    sm.s.fsp[p][c] = make_float2(fmaxf(f2.x + b1c, 0.f),
                                                 fmaxf(f2.y + b1c, 0.f));
                }
            }
            __syncthreads();

            // Phase F: slots_new = hnew + fsp @ W2T + b2 -> global; then signal
            {
                u64 aO[4];
                #pragma unroll
                for (int p = 0; p < 4; p++) aO[p] = 0ULL;
                const float4* wp = g_W2T4 + c;
                float4 cw = ldcg4(wp);
                for (int kq = 0; kq < 64; kq++) {
                    float4 nw = ldcg4(wp + (size_t)(kq < 63 ? kq + 1 : 63) * Dd);
                    int k = 4 * kq;
                    u64 d0 = dup2(cw.x), d1 = dup2(cw.y), d2 = dup2(cw.z), d3 = dup2(cw.w);
                    #pragma unroll
                    for (int p = 0; p < 4; p++) {
                        ulonglong2 x2a = *(const ulonglong2*)&sm.s.fsp[p][k];
                        ulonglong2 x2b = *(const ulonglong2*)&sm.s.fsp[p][k + 2];
                        fma2(aO[p], x2a.x, d0); fma2(aO[p], x2a.y, d1);
                        fma2(aO[p], x2b.x, d2); fma2(aO[p], x2b.y, d3);
                    }
                    cw = nw;
                }
                float b2c = b2[c];
                bool last = (iter == NFr * 3 - 1);
                #pragma unroll
                for (int p = 0; p < 4; p++) {
                    float2 o2 = unpk(aO[p]);
                    float snlo = hnlo[p] + o2.x + b2c;
                    float snhi = hnhi[p] + o2.y + b2c;
                    int rlo = i0 + 2 * p;
                    g_slots[((size_t)b * Ss + rlo) * Dd + c] = snlo;
                    if (2 * p + 1 < RS) g_slots[((size_t)b * Ss + rlo + 1) * Dd + c] = snhi;
                    if (last) {
                        if (rlo < NA)
                            out_slots[((size_t)b * NA + rlo) * Dd + c] = snlo;
                        if (2 * p + 1 < RS && rlo + 1 < NA)
                            out_slots[((size_t)b * NA + rlo + 1) * Dd + c] = snhi;
                    }
                }
            }
            signal(&g_slot_done[b]);
        }
    }
}

// ---------------- launch ------------------------------------------------------
extern "C" void kernel_launch(void* const* d_in, const int* in_sizes, int n_in,
                              void* d_out, int out_size) {
    const float* inputs = (const float*)d_in[0];
    const float* noise  = (const float*)d_in[1];
    const float* mu     = (const float*)d_in[2];
    const float* sigma  = (const float*)d_in[3];
    const float* Wq     = (const float*)d_in[4];
    const float* bq     = (const float*)d_in[5];
    const float* Wk     = (const float*)d_in[6];
    const float* bk     = (const float*)d_in[7];
    const float* Wv     = (const float*)d_in[8];
    const float* bv     = (const float*)d_in[9];
    const float* W1     = (const float*)d_in[10];
    const float* b1     = (const float*)d_in[11];
    const float* W2     = (const float*)d_in[12];
    const float* b2     = (const float*)d_in[13];
    const float* W_ih   = (const float*)d_in[14];
    const float* b_ih   = (const float*)d_in[15];
    const float* W_hh   = (const float*)d_in[16];
    const float* b_hh   = (const float*)d_in[17];
    const float* gin    = (const float*)d_in[18];
    const float* bein   = (const float*)d_in[19];
    const float* gsl    = (const float*)d_in[20];
    const float* besl   = (const float*)d_in[21];
    const float* gff    = (const float*)d_in[22];
    const float* beff   = (const float*)d_in[23];

    float* out = (float*)d_out;
    float* out_attn = out + (size_t)Bz * NA * Dd;

    setup_kernel<<<344, dim3(32, 8)>>>(Wq, Wk, Wv, W1, W2, W_ih, W_hh,
                                       noise, mu, sigma);
    kv_all_kernel<<<(Bz * NFr * Nn) / RLN, 256>>>(inputs, gin, bein, bk, bv);
    persist_kernel<<<Bz * 9, 256>>>(out, out_attn, b_ih, b_hh, gff, beff,
                                    b1, b2, gsl, besl, bq);
}

// round 16
// speedup vs baseline: 1.1213x; 1.0141x over previous
#include <cuda_runtime.h>
#include <math.h>

#define Bz 32
#define NFr 16
#define Dd 256
#define Ss 21
#define Nn 192
#define NA 20
#define EPSs 1e-8f
#define LN_EPS 1e-5f
#define RLN 24
#define RS 7

typedef unsigned long long u64;

// ---------------- packed f32x2 helpers ---------------------------------------
__device__ __forceinline__ void fma2(u64& d, u64 a, u64 b) {
    asm("fma.rn.f32x2 %0, %1, %2, %0;" : "+l"(d) : "l"(a), "l"(b));
}
__device__ __forceinline__ u64 dup2(float v) {
    u64 r; asm("mov.b64 %0, {%1, %1};" : "=l"(r) : "f"(v)); return r;
}
__device__ __forceinline__ float2 unpk(u64 v) {
    float lo, hi; asm("mov.b64 {%0, %1}, %2;" : "=f"(lo), "=f"(hi) : "l"(v));
    return make_float2(lo, hi);
}

// ---------------- scratch ----------------------------------------------------
__device__ float g_K[(size_t)Bz * NFr * Nn * Dd];
__device__ float4 g_V4[(size_t)Bz * NFr * (Nn / 4) * Dd];
__device__ float g_slots[Bz * Ss * Dd];
__device__ float g_Q[Bz * Ss * Dd];
__device__ float g_At[Bz * Nn * Ss];
__device__ unsigned g_dots_done[Bz];
__device__ unsigned g_slot_done[Bz];
__device__ unsigned g_q_done[Bz];
__device__ float4 g_WqT4[64 * Dd];
__device__ float4 g_WkT4[64 * Dd];
__device__ float4 g_WvT4[64 * Dd];
__device__ float4 g_W1T4[64 * Dd];
__device__ float4 g_W2T4[64 * Dd];
__device__ float4 g_WihT4[64 * 3 * Dd];
__device__ float4 g_WhhT4[64 * 3 * Dd];

__device__ __forceinline__ float4 ldcg4(const float4* p) { return __ldcg(p); }

// ---------------- sync helpers ------------------------------------------------
__device__ __forceinline__ void wait_ge(unsigned* p, unsigned tgt) {
    if (threadIdx.x == 0) {
        unsigned v;
        do {
            asm volatile("ld.acquire.gpu.global.u32 %0, [%1];"
                         : "=r"(v) : "l"(p) : "memory");
        } while (v < tgt);
    }
    __syncthreads();
}
__device__ __forceinline__ void signal(unsigned* p) {
    __syncthreads();
    if (threadIdx.x == 0) { __threadfence(); atomicAdd(p, 1u); }
}

// -------- setup: f4-transpose all weights + init slots + zero counters --------
__global__ void setup_kernel(const float* __restrict__ Wq, const float* __restrict__ Wk,
                             const float* __restrict__ Wv, const float* __restrict__ W1,
                             const float* __restrict__ W2, const float* __restrict__ Wih,
                             const float* __restrict__ Whh,
                             const float* __restrict__ noise,
                             const float* __restrict__ mu,
                             const float* __restrict__ sigma) {
    int bid = blockIdx.x;
    int tx = threadIdx.x, ty = threadIdx.y;
    if (bid < 176) {
        __shared__ float4 tile[32][33];
        const float4* src; float4* dst; int R; int tloc;
        if (bid < 80) {
            int m = bid / 16; tloc = bid % 16; R = 256;
            switch (m) {
                case 0: src = (const float4*)Wq; dst = g_WqT4; break;
                case 1: src = (const float4*)Wk; dst = g_WkT4; break;
                case 2: src = (const float4*)Wv; dst = g_WvT4; break;
                case 3: src = (const float4*)W1; dst = g_W1T4; break;
                default: src = (const float4*)W2; dst = g_W2T4; break;
            }
        } else {
            int m = (bid - 80) / 48; tloc = (bid - 80) % 48; R = 768;
            src = (const float4*)(m == 0 ? Wih : Whh);
            dst = (m == 0 ? g_WihT4 : g_WhhT4);
        }
        int bx = (tloc & 1) * 32;
        int by = (tloc >> 1) * 32;
        #pragma unroll
        for (int i = 0; i < 32; i += 8)
            tile[ty + i][tx] = src[(size_t)(by + ty + i) * 64 + bx + tx];
        __syncthreads();
        #pragma unroll
        for (int i = 0; i < 32; i += 8)
            dst[(size_t)(bx + ty + i) * R + by + tx] = tile[tx][ty + i];
    } else {
        int t = ty * 32 + tx;
        int base = (bid - 176) * 1024 + t;
        #pragma unroll
        for (int u = 0; u < 4; u++) {
            int idx = base + u * 256;
            int d = idx & (Dd - 1);
            g_slots[idx] = mu[d] + sigma[d] * noise[idx];
        }
        if (bid == 176 && t < Bz) {
            g_dots_done[t] = 0u; g_slot_done[t] = 0u; g_q_done[t] = 0u;
        }
    }
}

// ---------------- warp helpers ------------------------------------------------
__device__ __forceinline__ float warp_sum(float v) {
    #pragma unroll
    for (int o = 16; o > 0; o >>= 1) v += __shfl_xor_sync(0xffffffffu, v, o);
    return v;
}
__device__ __forceinline__ float warp_max(float v) {
    #pragma unroll
    for (int o = 16; o > 0; o >>= 1) v = fmaxf(v, __shfl_xor_sync(0xffffffffu, v, o));
    return v;
}

// ------- LN(all frames) -> K, V4.  grid = B*NF*N/RLN = 4096 ------------------
__global__ __launch_bounds__(256)
void kv_all_kernel(const float* __restrict__ inputs,
                   const float* __restrict__ gam, const float* __restrict__ bet,
                   const float* __restrict__ bk, const float* __restrict__ bv) {
    __shared__ float2 xs2[RLN / 2][Dd];
    int row0 = blockIdx.x * RLN;
    int t = threadIdx.x, w = t >> 5, l = t & 31;

    for (int rr = w; rr < RLN; rr += 8) {
        int row = row0 + rr;
        const float* src = inputs + (size_t)row * Dd;
        float v[8]; float s = 0.f;
        #pragma unroll
        for (int u = 0; u < 8; u++) { v[u] = src[l + 32 * u]; s += v[u]; }
        s = warp_sum(s);
        float m = s * (1.0f / Dd);
        float vs = 0.f;
        #pragma unroll
        for (int u = 0; u < 8; u++) { v[u] -= m; vs += v[u] * v[u]; }
        vs = warp_sum(vs);
        float inv = rsqrtf(vs * (1.0f / Dd) + LN_EPS);
        int p = rr >> 1, e = rr & 1;
        #pragma unroll
        for (int u = 0; u < 8; u++) {
            int k = l + 32 * u;
            ((float*)xs2)[((size_t)p * Dd + k) * 2 + e] = v[u] * inv * gam[k] + bet[k];
        }
    }
    __syncthreads();

    int c = t;
    u64 aK[RLN / 2], aV[RLN / 2];
    #pragma unroll
    for (int p = 0; p < RLN / 2; p++) { aK[p] = 0ULL; aV[p] = 0ULL; }
    const float4* wk4 = g_WkT4 + c;
    const float4* wv4 = g_WvT4 + c;
    float4 ck = wk4[0], cv = wv4[0];
    for (int kq = 0; kq < 64; kq++) {
        int nx = (kq < 63 ? kq + 1 : 63) * Dd;
        float4 nk = wk4[nx], nv = wv4[nx];
        int k = 4 * kq;
        u64 dk0 = dup2(ck.x), dk1 = dup2(ck.y), dk2 = dup2(ck.z), dk3 = dup2(ck.w);
        u64 dv0 = dup2(cv.x), dv1 = dup2(cv.y), dv2 = dup2(cv.z), dv3 = dup2(cv.w);
        #pragma unroll
        for (int p = 0; p < RLN / 2; p++) {
            ulonglong2 x2a = *(const ulonglong2*)&xs2[p][k];
            ulonglong2 x2b = *(const ulonglong2*)&xs2[p][k + 2];
            fma2(aK[p], x2a.x, dk0); fma2(aK[p], x2a.y, dk1);
            fma2(aK[p], x2b.x, dk2); fma2(aK[p], x2b.y, dk3);
            fma2(aV[p], x2a.x, dv0); fma2(aV[p], x2a.y, dv1);
            fma2(aV[p], x2b.x, dv2); fma2(aV[p], x2b.y, dv3);
        }
        ck = nk; cv = nv;
    }
    float bkc = bk[c], bvc = bv[c];
    #pragma unroll
    for (int p = 0; p < RLN / 2; p++) {
        float2 k2 = unpk(aK[p]);
        g_K[(size_t)(row0 + 2 * p) * Dd + c]     = k2.x + bkc;
        g_K[(size_t)(row0 + 2 * p + 1) * Dd + c] = k2.y + bkc;
    }
    #pragma unroll
    for (int q = 0; q < RLN / 4; q++) {
        float2 a = unpk(aV[2 * q]);
        float2 bqv = unpk(aV[2 * q + 1]);
        float4 vq = make_float4(a.x + bvc, a.y + bvc, bqv.x + bvc, bqv.y + bvc);
        g_V4[((size_t)(row0 / 4) + q) * Dd + c] = vq;
    }
}

// ---------------- persistent kernel: all 48 iterations ------------------------
// grid = Bz * 9. roles 0-5: dots (32 j + distributed Q rows, iter 0 included).
// roles 6-8: slot updates (7 rows each; final iter also writes d_out slots).
union SMem {
    struct { float Ks[2][32][68]; float Qs[2][Ss][64]; float ds[32][24];
             float xq[4][Dd]; } d;                                     // ~35.4KB
    struct { float2 asp[4][Nn]; float2 usp[4][Dd]; float2 hsp[4][Dd];
             float2 fsp[4][Dd]; float inv_[8]; } s;
};

__global__ __launch_bounds__(256, 2)
void persist_kernel(float* __restrict__ out_slots, float* __restrict__ out_attn,
                    const float* __restrict__ b_ih, const float* __restrict__ b_hh,
                    const float* __restrict__ g_ff, const float* __restrict__ be_ff,
                    const float* __restrict__ b1, const float* __restrict__ b2,
                    const float* __restrict__ g_sl, const float* __restrict__ be_sl,
                    const float* __restrict__ bq) {
    __shared__ SMem sm;
    int b = blockIdx.x / 9;
    int role = blockIdx.x % 9;
    int t = threadIdx.x, w = t >> 5, l = t & 31;

    if (role < 6) {
        // ================= DOTS block =================
        int j0 = role * 32;
        int jj = l;
        int i0 = w, i1 = w + 8, i2 = w + 16;
        bool has2 = (i2 < Ss);
        // Q-row assignment: roles 0-2 -> 4 rows, roles 3-5 -> 3 rows
        int nr  = (role < 3) ? 4 : 3;
        int qs0 = (role < 3) ? role * 4 : 12 + (role - 3) * 3;

        for (int iter = 0; iter < NFr * 3; iter++) {
            int f = iter / 3, it = iter - 3 * f;
            const float* Kbase = g_K + (((size_t)b * NFr + f) * Nn) * Dd;

            // ---- prefetch K chunk 0 (depends only on f; hides behind wait) --
            for (int idx = t; idx < 32 * 16; idx += 256) {
                int r = idx >> 4, kk4 = (idx & 15) * 4;
                *(float4*)&sm.d.Ks[0][r][kk4] =
                    *(const float4*)&Kbase[(size_t)(j0 + r) * Dd + kk4];
            }

            // ---- Q-phase (every iter; iter 0 reads slots0) ----
            {
                wait_ge(&g_slot_done[b], 3u * iter);
                if (w < nr) {
                    int row = qs0 + w;
                    const float* src = g_slots + ((size_t)b * Ss + row) * Dd;
                    float v[8]; float s = 0.f;
                    #pragma unroll
                    for (int u = 0; u < 8; u++) { v[u] = __ldcg(&src[l + 32 * u]); s += v[u]; }
                    s = warp_sum(s);
                    float m = s * (1.0f / Dd);
                    float vs = 0.f;
                    #pragma unroll
                    for (int u = 0; u < 8; u++) { v[u] -= m; vs += v[u] * v[u]; }
                    vs = warp_sum(vs);
                    float iv = rsqrtf(vs * (1.0f / Dd) + LN_EPS);
                    #pragma unroll
                    for (int u = 0; u < 8; u++) {
                        int k = l + 32 * u;
                        sm.d.xq[w][k] = v[u] * iv * g_sl[k] + be_sl[k];
                    }
                }
                if (nr < 4 && w == 4) {  // zero pad row 3
                    #pragma unroll
                    for (int u = 0; u < 8; u++) sm.d.xq[3][l + 32 * u] = 0.f;
                }
                __syncthreads();
                {
                    int c = t;
                    float acc[4];
                    float bqc = bq[c];
                    #pragma unroll
                    for (int r = 0; r < 4; r++) acc[r] = bqc;
                    const float4* wp = g_WqT4 + c;
                    float4 cw = ldcg4(wp);
                    for (int kq = 0; kq < 64; kq++) {
                        float4 nw = ldcg4(wp + (size_t)(kq < 63 ? kq + 1 : 63) * Dd);
                        int k = 4 * kq;
                        #pragma unroll
                        for (int r = 0; r < 4; r++) {
                            float4 x4 = *(const float4*)&sm.d.xq[r][k];
                            acc[r] = fmaf(x4.x, cw.x, acc[r]);
                            acc[r] = fmaf(x4.y, cw.y, acc[r]);
                            acc[r] = fmaf(x4.z, cw.z, acc[r]);
                            acc[r] = fmaf(x4.w, cw.w, acc[r]);
                        }
                        cw = nw;
                    }
                    for (int r = 0; r < nr; r++)
                        g_Q[((size_t)b * Ss + qs0 + r) * Dd + c] = acc[r];
                }
                signal(&g_q_done[b]);
                wait_ge(&g_q_done[b], 6u * (iter + 1));
            }

            // ---- dots main: 4 chunks of 64 cols, ping-pong double buffer ----
            for (int idx = t; idx < Ss * 16; idx += 256) {
                int r = idx >> 4, kk4 = (idx & 15) * 4;
                *(float4*)&sm.d.Qs[0][r][kk4] =
                    __ldcg((const float4*)&g_Q[((size_t)b * Ss + r) * Dd + kk4]);
            }
            __syncthreads();
            u64 A0 = 0ULL, A1 = 0ULL, A2 = 0ULL;
            #pragma unroll
            for (int ch = 0; ch < 4; ch++) {
                int cb = ch & 1, nb = cb ^ 1;
                if (ch < 3) {
                    int k0 = (ch + 1) * 64;
                    for (int idx = t; idx < 32 * 16; idx += 256) {
                        int r = idx >> 4, kk4 = (idx & 15) * 4;
                        *(float4*)&sm.d.Ks[nb][r][kk4] =
                            *(const float4*)&Kbase[(size_t)(j0 + r) * Dd + k0 + kk4];
                    }
                    for (int idx = t; idx < Ss * 16; idx += 256) {
                        int r = idx >> 4, kk4 = (idx & 15) * 4;
                        *(float4*)&sm.d.Qs[nb][r][kk4] =
                            __ldcg((const float4*)&g_Q[((size_t)b * Ss + r) * Dd + k0 + kk4]);
                    }
                }
                #pragma unroll
                for (int kk = 0; kk < 64; kk += 4) {
                    ulonglong2 kp = *(const ulonglong2*)&sm.d.Ks[cb][jj][kk];
                    ulonglong2 q0 = *(const ulonglong2*)&sm.d.Qs[cb][i0][kk];
                    ulonglong2 q1 = *(const ulonglong2*)&sm.d.Qs[cb][i1][kk];
                    fma2(A0, kp.x, q0.x); fma2(A0, kp.y, q0.y);
                    fma2(A1, kp.x, q1.x); fma2(A1, kp.y, q1.y);
                    if (has2) {
                        ulonglong2 q2 = *(const ulonglong2*)&sm.d.Qs[cb][i2][kk];
                        fma2(A2, kp.x, q2.x); fma2(A2, kp.y, q2.y);
                    }
                }
                __syncthreads();
            }
            float2 s0 = unpk(A0), s1 = unpk(A1);
            sm.d.ds[jj][i0] = (s0.x + s0.y) * 0.0625f;
            sm.d.ds[jj][i1] = (s1.x + s1.y) * 0.0625f;
            if (has2) { float2 s2 = unpk(A2); sm.d.ds[jj][i2] = (s2.x + s2.y) * 0.0625f; }
            __syncthreads();
            for (int q = w; q < 32; q += 8) {
                float v = (l < Ss) ? sm.d.ds[q][l] : -3.4e38f;
                float mx = warp_max(v);
                float e = (l < Ss) ? expf(v - mx) : 0.f;
                float smv = warp_sum(e);
                if (l < Ss) {
                    float a = e / smv + EPSs;
                    g_At[((size_t)b * Nn + j0 + q) * Ss + l] = a;
                    if (it == 2)
                        out_attn[(((size_t)b * NFr + f) * Ss + l) * Nn + j0 + q] = a;
                }
            }
            __syncthreads();
            signal(&g_dots_done[b]);
        }
    } else {
        // ================= SLOT block =================
        int i0 = (role - 6) * RS;
        int c = t;
        for (int iter = 0; iter < NFr * 3; iter++) {
            int f = iter / 3;

            // ---- EARLY: h0 + h-side GRU gates (overlaps dots+Q) ----
            float h0lo[4], h0hi[4];
            #pragma unroll
            for (int p = 0; p < 4; p++) {
                int rlo = 2 * p, rhi = (2 * p + 1 < RS) ? 2 * p + 1 : RS - 1;
                h0lo[p] = g_slots[((size_t)b * Ss + i0 + rlo) * Dd + c];
                h0hi[p] = g_slots[((size_t)b * Ss + i0 + rhi) * Dd + c];
            }
            #pragma unroll
            for (int p = 0; p < 4; p++) sm.s.hsp[p][c] = make_float2(h0lo[p], h0hi[p]);
            __syncthreads();

            u64 a_hr[4], a_hz[4], a_hn[4];
            #pragma unroll
            for (int p = 0; p < 4; p++) { a_hr[p] = 0ULL; a_hz[p] = 0ULL; a_hn[p] = 0ULL; }
            {
                const float4* wh4 = g_WhhT4 + c;
                float4 cvr = ldcg4(wh4), cvz = ldcg4(wh4 + Dd), cvn = ldcg4(wh4 + 2 * Dd);
                for (int kq = 0; kq < 64; kq++) {
                    size_t nx = (size_t)(kq < 63 ? kq + 1 : 63) * (3 * Dd);
                    float4 nvr = ldcg4(wh4 + nx), nvz = ldcg4(wh4 + nx + Dd),
                           nvn = ldcg4(wh4 + nx + 2 * Dd);
                    int k = 4 * kq;
                    #pragma unroll
                    for (int p = 0; p < 4; p++) {
                        ulonglong2 h2a = *(const ulonglong2*)&sm.s.hsp[p][k];
                        ulonglong2 h2b = *(const ulonglong2*)&sm.s.hsp[p][k + 2];
                        fma2(a_hr[p], h2a.x, dup2(cvr.x)); fma2(a_hr[p], h2a.y, dup2(cvr.y));
                        fma2(a_hr[p], h2b.x, dup2(cvr.z)); fma2(a_hr[p], h2b.y, dup2(cvr.w));
                        fma2(a_hz[p], h2a.x, dup2(cvz.x)); fma2(a_hz[p], h2a.y, dup2(cvz.y));
                        fma2(a_hz[p], h2b.x, dup2(cvz.z)); fma2(a_hz[p], h2b.y, dup2(cvz.w));
                        fma2(a_hn[p], h2a.x, dup2(cvn.x)); fma2(a_hn[p], h2a.y, dup2(cvn.y));
                        fma2(a_hn[p], h2b.x, dup2(cvn.z)); fma2(a_hn[p], h2b.y, dup2(cvn.w));
                    }
                    cvr = nvr; cvz = nvz; cvn = nvn;
                }
            }

            wait_ge(&g_dots_done[b], 6u * (iter + 1));

            // Phase A: stage attn + row sums
            for (int idx = t; idx < 8 * Nn; idx += 256) {
                int lr = idx & 7, j = idx >> 3;
                int row = (lr < 7) ? lr : 6;
                ((float*)sm.s.asp)[((size_t)(lr >> 1) * Nn + j) * 2 + (lr & 1)] =
                    __ldcg(&g_At[((size_t)b * Nn + j) * Ss + i0 + row]);
            }
            __syncthreads();
            {
                int p = w >> 1, e = w & 1;
                float s = 0.f;
                #pragma unroll
                for (int u = 0; u < Nn / 32; u++)
                    s += ((const float*)sm.s.asp)[((size_t)p * Nn + l + 32 * u) * 2 + e];
                s = warp_sum(s);
                if (l == 0) sm.s.inv_[w] = 1.0f / s;
            }
            __syncthreads();

            // Phase B: updates = (A/rowsum) @ V
            u64 accU[4];
            #pragma unroll
            for (int p = 0; p < 4; p++) accU[p] = 0ULL;
            const float4* vp4 = g_V4 + (((size_t)b * NFr + f) * (Nn / 4)) * Dd + c;
            float4 cvv = vp4[0];
            for (int nq = 0; nq < Nn / 4; nq++) {
                float4 nvv = vp4[(size_t)(nq < Nn / 4 - 1 ? nq + 1 : nq) * Dd];
                int j = 4 * nq;
                u64 vd0 = dup2(cvv.x), vd1 = dup2(cvv.y);
                u64 vd2 = dup2(cvv.z), vd3 = dup2(cvv.w);
                #pragma unroll
                for (int p = 0; p < 4; p++) {
                    ulonglong2 a2a = *(const ulonglong2*)&sm.s.asp[p][j];
                    ulonglong2 a2b = *(const ulonglong2*)&sm.s.asp[p][j + 2];
                    fma2(accU[p], a2a.x, vd0); fma2(accU[p], a2a.y, vd1);
                    fma2(accU[p], a2b.x, vd2); fma2(accU[p], a2b.y, vd3);
                }
                cvv = nvv;
            }
            #pragma unroll
            for (int p = 0; p < 4; p++) {
                float2 u2 = unpk(accU[p]);
                sm.s.usp[p][c] = make_float2(u2.x * sm.s.inv_[2 * p],
                                             u2.y * sm.s.inv_[2 * p + 1]);
            }
            __syncthreads();

            // Phase C: u-side GRU gates
            u64 a_ir[4], a_iz[4], a_in[4];
            #pragma unroll
            for (int p = 0; p < 4; p++) { a_ir[p] = 0ULL; a_iz[p] = 0ULL; a_in[p] = 0ULL; }
            {
                const float4* wi4 = g_WihT4 + c;
                float4 cwr = ldcg4(wi4), cwz = ldcg4(wi4 + Dd), cwn = ldcg4(wi4 + 2 * Dd);
                for (int kq = 0; kq < 64; kq++) {
                    size_t nx = (size_t)(kq < 63 ? kq + 1 : 63) * (3 * Dd);
                    float4 nwr = ldcg4(wi4 + nx), nwz = ldcg4(wi4 + nx + Dd),
                           nwn = ldcg4(wi4 + nx + 2 * Dd);
                    int k = 4 * kq;
                    #pragma unroll
                    for (int p = 0; p < 4; p++) {
                        ulonglong2 u2a = *(const ulonglong2*)&sm.s.usp[p][k];
                        ulonglong2 u2b = *(const ulonglong2*)&sm.s.usp[p][k + 2];
                        fma2(a_ir[p], u2a.x, dup2(cwr.x)); fma2(a_ir[p], u2a.y, dup2(cwr.y));
                        fma2(a_ir[p], u2b.x, dup2(cwr.z)); fma2(a_ir[p], u2b.y, dup2(cwr.w));
                        fma2(a_iz[p], u2a.x, dup2(cwz.x)); fma2(a_iz[p], u2a.y, dup2(cwz.y));
                        fma2(a_iz[p], u2b.x, dup2(cwz.z)); fma2(a_iz[p], u2b.y, dup2(cwz.w));
                        fma2(a_in[p], u2a.x, dup2(cwn.x)); fma2(a_in[p], u2a.y, dup2(cwn.y));
                        fma2(a_in[p], u2b.x, dup2(cwn.z)); fma2(a_in[p], u2b.y, dup2(cwn.w));
                    }
                    cwr = nwr; cwz = nwz; cwn = nwn;
                }
            }
            float bir = b_ih[c], biz = b_ih[Dd + c], bin = b_ih[2 * Dd + c];
            float bhr = b_hh[c], bhz = b_hh[Dd + c], bhn = b_hh[2 * Dd + c];
            float hnlo[4], hnhi[4];
            #pragma unroll
            for (int p = 0; p < 4; p++) {
                float2 ir2 = unpk(a_ir[p]), iz2 = unpk(a_iz[p]), in2 = unpk(a_in[p]);
                float2 hr2 = unpk(a_hr[p]), hz2 = unpk(a_hz[p]), hn2 = unpk(a_hn[p]);
                {
                    float rg = 1.f / (1.f + expf(-(ir2.x + bir + hr2.x + bhr)));
                    float zg = 1.f / (1.f + expf(-(iz2.x + biz + hz2.x + bhz)));
                    float ng = tanhf(in2.x + bin + rg * (hn2.x + bhn));
                    hnlo[p] = (1.f - zg) * ng + zg * h0lo[p];
                }
                {
                    float rg = 1.f / (1.f + expf(-(ir2.y + bir + hr2.y + bhr)));
                    float zg = 1.f / (1.f + expf(-(iz2.y + biz + hz2.y + bhz)));
                    float ng = tanhf(in2.y + bin + rg * (hn2.y + bhn));
                    hnhi[p] = (1.f - zg) * ng + zg * h0hi[p];
                }
            }
            __syncthreads();
            #pragma unroll
            for (int p = 0; p < 4; p++) sm.s.usp[p][c] = make_float2(hnlo[p], hnhi[p]);
            __syncthreads();

            // Phase D: LN(hnew; g_ff) -> hsp
            {
                int p = w >> 1, e = w & 1;
                float v[8]; float s = 0.f;
                #pragma unroll
                for (int u = 0; u < 8; u++) {
                    v[u] = ((const float*)sm.s.usp)[((size_t)p * Dd + l + 32 * u) * 2 + e];
                    s += v[u];
                }
                s = warp_sum(s);
                float m = s * (1.0f / Dd);
                float vs = 0.f;
                #pragma unroll
                for (int u = 0; u < 8; u++) { v[u] -= m; vs += v[u] * v[u]; }
                vs = warp_sum(vs);
                float iv = rsqrtf(vs * (1.0f / Dd) + LN_EPS);
                #pragma unroll
                for (int u = 0; u < 8; u++) {
                    int k = l + 32 * u;
                    ((float*)sm.s.hsp)[((size_t)p * Dd + k) * 2 + e] =
                        v[u] * iv * g_ff[k] + be_ff[k];
                }
            }
            __syncthreads();

            // Phase E: FF = relu(LN @ W1T + b1) -> fsp
            {
                u64 aF[4];
                #pragma unroll
                for (int p = 0; p < 4; p++) aF[p] = 0ULL;
                const float4* wp = g_W1T4 + c;
                float4 cw = ldcg4(wp);
                for (int kq = 0; kq < 64; kq++) {
                    float4 nw = ldcg4(wp + (size_t)(kq < 63 ? kq + 1 : 63) * Dd);
                    int k = 4 * kq;
                    u64 d0 = dup2(cw.x), d1 = dup2(cw.y), d2 = dup2(cw.z), d3 = dup2(cw.w);
                    #pragma unroll
                    for (int p = 0; p < 4; p++) {
                        ulonglong2 x2a = *(const ulonglong2*)&sm.s.hsp[p][k];
                        ulonglong2 x2b = *(const ulonglong2*)&sm.s.hsp[p][k + 2];
                        fma2(aF[p], x2a.x, d0); fma2(aF[p], x2a.y, d1);
                        fma2(aF[p], x2b.x, d2); fma2(aF[p], x2b.y, d3);
                    }
                    cw = nw;
                }
                float b1c = b1[c];
                #pragma unroll
                for (int p = 0; p < 4; p++) {
                    float2 f2 = unpk(aF[p]);
                    sm.s.fsp[p][c] = make_float2(fmaxf(f2.x + b1c, 0.f),
                                                 fmaxf(f2.y + b1c, 0.f));
                }
            }
            __syncthreads();

            // Phase F: slots_new = hnew + fsp @ W2T + b2 -> global; then signal
            {
                u64 aO[4];
                #pragma unroll
                for (int p = 0; p < 4; p++) aO[p] = 0ULL;
                const float4* wp = g_W2T4 + c;
                float4 cw = ldcg4(wp);
                for (int kq = 0; kq < 64; kq++) {
                    float4 nw = ldcg4(wp + (size_t)(kq < 63 ? kq + 1 : 63) * Dd);
                    int k = 4 * kq;
                    u64 d0 = dup2(cw.x), d1 = dup2(cw.y), d2 = dup2(cw.z), d3 = dup2(cw.w);
                    #pragma unroll
                    for (int p = 0; p < 4; p++) {
                        ulonglong2 x2a = *(const ulonglong2*)&sm.s.fsp[p][k];
                        ulonglong2 x2b = *(const ulonglong2*)&sm.s.fsp[p][k + 2];
                        fma2(aO[p], x2a.x, d0); fma2(aO[p], x2a.y, d1);
                        fma2(aO[p], x2b.x, d2); fma2(aO[p], x2b.y, d3);
                    }
                    cw = nw;
                }
                float b2c = b2[c];
                bool last = (iter == NFr * 3 - 1);
                #pragma unroll
                for (int p = 0; p < 4; p++) {
                    float2 o2 = unpk(aO[p]);
                    float snlo = hnlo[p] + o2.x + b2c;
                    float snhi = hnhi[p] + o2.y + b2c;
                    int rlo = i0 + 2 * p;
                    g_slots[((size_t)b * Ss + rlo) * Dd + c] = snlo;
                    if (2 * p + 1 < RS) g_slots[((size_t)b * Ss + rlo + 1) * Dd + c] = snhi;
                    if (last) {
                        if (rlo < NA)
                            out_slots[((size_t)b * NA + rlo) * Dd + c] = snlo;
                        if (2 * p + 1 < RS && rlo + 1 < NA)
                            out_slots[((size_t)b * NA + rlo + 1) * Dd + c] = snhi;
                    }
                }
            }
            signal(&g_slot_done[b]);
        }
    }
}

// ---------------- launch ------------------------------------------------------
extern "C" void kernel_launch(void* const* d_in, const int* in_sizes, int n_in,
                              void* d_out, int out_size) {
    const float* inputs = (const float*)d_in[0];
    const float* noise  = (const float*)d_in[1];
    const float* mu     = (const float*)d_in[2];
    const float* sigma  = (const float*)d_in[3];
    const float* Wq     = (const float*)d_in[4];
    const float* bq     = (const float*)d_in[5];
    const float* Wk     = (const float*)d_in[6];
    const float* bk     = (const float*)d_in[7];
    const float* Wv     = (const float*)d_in[8];
    const float* bv     = (const float*)d_in[9];
    const float* W1     = (const float*)d_in[10];
    const float* b1     = (const float*)d_in[11];
    const float* W2     = (const float*)d_in[12];
    const float* b2     = (const float*)d_in[13];
    const float* W_ih   = (const float*)d_in[14];
    const float* b_ih   = (const float*)d_in[15];
    const float* W_hh   = (const float*)d_in[16];
    const float* b_hh   = (const float*)d_in[17];
    const float* gin    = (const float*)d_in[18];
    const float* bein   = (const float*)d_in[19];
    const float* gsl    = (const float*)d_in[20];
    const float* besl   = (const float*)d_in[21];
    const float* gff    = (const float*)d_in[22];
    const float* beff   = (const float*)d_in[23];

    float* out = (float*)d_out;
    float* out_attn = out + (size_t)Bz * NA * Dd;

    setup_kernel<<<344, dim3(32, 8)>>>(Wq, Wk, Wv, W1, W2, W_ih, W_hh,
                                       noise, mu, sigma);
    kv_all_kernel<<<(Bz * NFr * Nn) / RLN, 256>>>(inputs, gin, bein, bk, bv);
    persist_kernel<<<Bz * 9, 256>>>(out, out_attn, b_ih, b_hh, gff, beff,
                                    b1, b2, gsl, besl, bq);
}

// round 17
// speedup vs baseline: 1.2719x; 1.1343x over previous
#include <cuda_runtime.h>
#include <math.h>

#define Bz 32
#define NFr 16
#define Dd 256
#define Ss 21
#define Nn 192
#define NA 20
#define EPSs 1e-8f
#define LN_EPS 1e-5f
#define RLN 24
#define RS 7

typedef unsigned long long u64;

// ---------------- packed f32x2 helpers ---------------------------------------
__device__ __forceinline__ void fma2(u64& d, u64 a, u64 b) {
    asm("fma.rn.f32x2 %0, %1, %2, %0;" : "+l"(d) : "l"(a), "l"(b));
}
__device__ __forceinline__ u64 dup2(float v) {
    u64 r; asm("mov.b64 %0, {%1, %1};" : "=l"(r) : "f"(v)); return r;
}
__device__ __forceinline__ float2 unpk(u64 v) {
    float lo, hi; asm("mov.b64 {%0, %1}, %2;" : "=f"(lo), "=f"(hi) : "l"(v));
    return make_float2(lo, hi);
}

// ---------------- scratch ----------------------------------------------------
__device__ float g_K[(size_t)Bz * NFr * Nn * Dd];
__device__ float4 g_V4[(size_t)Bz * NFr * (Nn / 4) * Dd];
__device__ float g_slots[Bz * Ss * Dd];
__device__ float g_Q[Bz * Ss * Dd];
__device__ float g_At[Bz * Nn * Ss];
__device__ unsigned g_dots_done[Bz];
__device__ unsigned g_slot_done[Bz];
__device__ unsigned g_q_done[Bz];
__device__ unsigned g_kv_ready[Bz * NFr];   // chunks done per (b,f); target 8 (f>=2)
__device__ float4 g_WqT4[64 * Dd];
__device__ float4 g_WkT4[64 * Dd];
__device__ float4 g_WvT4[64 * Dd];
__device__ float4 g_W1T4[64 * Dd];
__device__ float4 g_W2T4[64 * Dd];
__device__ float4 g_WihT4[64 * 3 * Dd];
__device__ float4 g_WhhT4[64 * 3 * Dd];

__device__ __forceinline__ float4 ldcg4(const float4* p) { return __ldcg(p); }

// ---------------- sync helpers ------------------------------------------------
__device__ __forceinline__ void wait_ge(unsigned* p, unsigned tgt) {
    if (threadIdx.x == 0) {
        unsigned v;
        do {
            asm volatile("ld.acquire.gpu.global.u32 %0, [%1];"
                         : "=r"(v) : "l"(p) : "memory");
        } while (v < tgt);
    }
    __syncthreads();
}
__device__ __forceinline__ void signal(unsigned* p) {
    __syncthreads();
    if (threadIdx.x == 0) { __threadfence(); atomicAdd(p, 1u); }
}

// ---------------- warp helpers ------------------------------------------------
__device__ __forceinline__ float warp_sum(float v) {
    #pragma unroll
    for (int o = 16; o > 0; o >>= 1) v += __shfl_xor_sync(0xffffffffu, v, o);
    return v;
}
__device__ __forceinline__ float warp_max(float v) {
    #pragma unroll
    for (int o = 16; o > 0; o >>= 1) v = fmaxf(v, __shfl_xor_sync(0xffffffffu, v, o));
    return v;
}

// ------- KV chunk body: LN(inputs rows row0..row0+23) -> K, V4 ---------------
__device__ void kv_chunk_body(int row0, float2 (*xs2)[Dd],
                              const float* __restrict__ inputs,
                              const float* __restrict__ gam, const float* __restrict__ bet,
                              const float* __restrict__ bk, const float* __restrict__ bv) {
    int t = threadIdx.x, w = t >> 5, l = t & 31;

    for (int rr = w; rr < RLN; rr += 8) {
        int row = row0 + rr;
        const float* src = inputs + (size_t)row * Dd;
        float v[8]; float s = 0.f;
        #pragma unroll
        for (int u = 0; u < 8; u++) { v[u] = src[l + 32 * u]; s += v[u]; }
        s = warp_sum(s);
        float m = s * (1.0f / Dd);
        float vs = 0.f;
        #pragma unroll
        for (int u = 0; u < 8; u++) { v[u] -= m; vs += v[u] * v[u]; }
        vs = warp_sum(vs);
        float inv = rsqrtf(vs * (1.0f / Dd) + LN_EPS);
        int p = rr >> 1, e = rr & 1;
        #pragma unroll
        for (int u = 0; u < 8; u++) {
            int k = l + 32 * u;
            ((float*)xs2)[((size_t)p * Dd + k) * 2 + e] = v[u] * inv * gam[k] + bet[k];
        }
    }
    __syncthreads();

    int c = t;
    u64 aK[RLN / 2], aV[RLN / 2];
    #pragma unroll
    for (int p = 0; p < RLN / 2; p++) { aK[p] = 0ULL; aV[p] = 0ULL; }
    const float4* wk4 = g_WkT4 + c;
    const float4* wv4 = g_WvT4 + c;
    float4 ck = wk4[0], cv = wv4[0];
    for (int kq = 0; kq < 64; kq++) {
        int nx = (kq < 63 ? kq + 1 : 63) * Dd;
        float4 nk = wk4[nx], nv = wv4[nx];
        int k = 4 * kq;
        u64 dk0 = dup2(ck.x), dk1 = dup2(ck.y), dk2 = dup2(ck.z), dk3 = dup2(ck.w);
        u64 dv0 = dup2(cv.x), dv1 = dup2(cv.y), dv2 = dup2(cv.z), dv3 = dup2(cv.w);
        #pragma unroll
        for (int p = 0; p < RLN / 2; p++) {
            ulonglong2 x2a = *(const ulonglong2*)&xs2[p][k];
            ulonglong2 x2b = *(const ulonglong2*)&xs2[p][k + 2];
            fma2(aK[p], x2a.x, dk0); fma2(aK[p], x2a.y, dk1);
            fma2(aK[p], x2b.x, dk2); fma2(aK[p], x2b.y, dk3);
            fma2(aV[p], x2a.x, dv0); fma2(aV[p], x2a.y, dv1);
            fma2(aV[p], x2b.x, dv2); fma2(aV[p], x2b.y, dv3);
        }
        ck = nk; cv = nv;
    }
    float bkc = bk[c], bvc = bv[c];
    #pragma unroll
    for (int p = 0; p < RLN / 2; p++) {
        float2 k2 = unpk(aK[p]);
        g_K[(size_t)(row0 + 2 * p) * Dd + c]     = k2.x + bkc;
        g_K[(size_t)(row0 + 2 * p + 1) * Dd + c] = k2.y + bkc;
    }
    #pragma unroll
    for (int q = 0; q < RLN / 4; q++) {
        float2 a = unpk(aV[2 * q]);
        float2 bqv = unpk(aV[2 * q + 1]);
        float4 vq = make_float4(a.x + bvc, a.y + bvc, bqv.x + bvc, bqv.y + bvc);
        g_V4[((size_t)(row0 / 4) + q) * Dd + c] = vq;
    }
}

// -------- setup: f4-transpose all weights + init slots + zero counters --------
__global__ void setup_kernel(const float* __restrict__ Wq, const float* __restrict__ Wk,
                             const float* __restrict__ Wv, const float* __restrict__ W1,
                             const float* __restrict__ W2, const float* __restrict__ Wih,
                             const float* __restrict__ Whh,
                             const float* __restrict__ noise,
                             const float* __restrict__ mu,
                             const float* __restrict__ sigma) {
    int bid = blockIdx.x;
    int tx = threadIdx.x, ty = threadIdx.y;
    if (bid < 176) {
        __shared__ float4 tile[32][33];
        const float4* src; float4* dst; int R; int tloc;
        if (bid < 80) {
            int m = bid / 16; tloc = bid % 16; R = 256;
            switch (m) {
                case 0: src = (const float4*)Wq; dst = g_WqT4; break;
                case 1: src = (const float4*)Wk; dst = g_WkT4; break;
                case 2: src = (const float4*)Wv; dst = g_WvT4; break;
                case 3: src = (const float4*)W1; dst = g_W1T4; break;
                default: src = (const float4*)W2; dst = g_W2T4; break;
            }
        } else {
            int m = (bid - 80) / 48; tloc = (bid - 80) % 48; R = 768;
            src = (const float4*)(m == 0 ? Wih : Whh);
            dst = (m == 0 ? g_WihT4 : g_WhhT4);
        }
        int bx = (tloc & 1) * 32;
        int by = (tloc >> 1) * 32;
        #pragma unroll
        for (int i = 0; i < 32; i += 8)
            tile[ty + i][tx] = src[(size_t)(by + ty + i) * 64 + bx + tx];
        __syncthreads();
        #pragma unroll
        for (int i = 0; i < 32; i += 8)
            dst[(size_t)(bx + ty + i) * R + by + tx] = tile[tx][ty + i];
    } else {
        int t = ty * 32 + tx;
        int base = (bid - 176) * 1024 + t;
        #pragma unroll
        for (int u = 0; u < 4; u++) {
            int idx = base + u * 256;
            int d = idx & (Dd - 1);
            g_slots[idx] = mu[d] + sigma[d] * noise[idx];
        }
        if (bid == 176) {
            if (t < Bz) { g_dots_done[t] = 0u; g_slot_done[t] = 0u; g_q_done[t] = 0u; }
            for (int i = t; i < Bz * NFr; i += 256) g_kv_ready[i] = 0u;
        }
    }
}

// ---------------- kv for frames 0-1 (pre-launch, 512 blocks) ------------------
__global__ __launch_bounds__(256)
void kv01_kernel(const float* __restrict__ inputs,
                 const float* __restrict__ gam, const float* __restrict__ bet,
                 const float* __restrict__ bk, const float* __restrict__ bv) {
    __shared__ float2 xs2[RLN / 2][Dd];
    int ci = blockIdx.x;                 // 512 = 32 b * 2 f * 8 chunks
    int b = ci >> 4, rem = ci & 15;
    int f = rem >> 3, n0 = (rem & 7) * RLN;
    int row0 = (b * NFr + f) * Nn + n0;
    kv_chunk_body(row0, xs2, inputs, gam, bet, bk, bv);
}

// ---------------- persistent kernel: all 48 iterations ------------------------
// grid = Bz * 9. roles 0-5: dots (+ distributed Q rows + opportunistic KV for
// frames 2..15). roles 6-8: slot updates (final iter writes d_out slots).
union SMem {
    struct { float Ks[2][32][68]; float Qs[2][Ss][64]; float ds[32][24];
             float xq[4][Dd]; } d;                                     // ~35.4KB
    struct { float2 asp[4][Nn]; float2 usp[4][Dd]; float2 hsp[4][Dd];
             float2 fsp[4][Dd]; float inv_[8]; } s;
    struct { float2 xs2[RLN / 2][Dd]; } kv;                            // 24KB
};

__global__ __launch_bounds__(256, 2)
void persist_kernel(float* __restrict__ out_slots, float* __restrict__ out_attn,
                    const float* __restrict__ inputs,
                    const float* __restrict__ gin, const float* __restrict__ bein,
                    const float* __restrict__ bk, const float* __restrict__ bv,
                    const float* __restrict__ b_ih, const float* __restrict__ b_hh,
                    const float* __restrict__ g_ff, const float* __restrict__ be_ff,
                    const float* __restrict__ b1, const float* __restrict__ b2,
                    const float* __restrict__ g_sl, const float* __restrict__ be_sl,
                    const float* __restrict__ bq) {
    __shared__ SMem sm;
    int b = blockIdx.x / 9;
    int role = blockIdx.x % 9;
    int t = threadIdx.x, w = t >> 5, l = t & 31;

    if (role < 6) {
        // ================= DOTS block =================
        int j0 = role * 32;
        int jj = l;
        int i0 = w, i1 = w + 8, i2 = w + 16;
        bool has2 = (i2 < Ss);
        int nr  = (role < 3) ? 4 : 3;
        int qs0 = (role < 3) ? role * 4 : 12 + (role - 3) * 3;

        for (int iter = 0; iter < NFr * 3; iter++) {
            int f = iter / 3, it = iter - 3 * f;
            const float* Kbase = g_K + (((size_t)b * NFr + f) * Nn) * Dd;

            // ---- opportunistic KV production for frames 2..15 ----
            if ((iter & 1) == 0) {
                int cdx = (iter >> 1) * 6 + role;
                if (cdx < 14 * 8) {
                    int fk = 2 + (cdx >> 3);
                    int n0 = (cdx & 7) * RLN;
                    int row0 = (b * NFr + fk) * Nn + n0;
                    kv_chunk_body(row0, sm.kv.xs2, inputs, gin, bein, bk, bv);
                    __syncthreads();
                    if (t == 0) { __threadfence(); atomicAdd(&g_kv_ready[b * NFr + fk], 1u); }
                    __syncthreads();
                }
            }
            if (f >= 2) wait_ge(&g_kv_ready[b * NFr + f], 8u);

            // ---- prefetch K chunk 0 (hides behind slot wait) ----
            for (int idx = t; idx < 32 * 16; idx += 256) {
                int r = idx >> 4, kk4 = (idx & 15) * 4;
                *(float4*)&sm.d.Ks[0][r][kk4] =
                    *(const float4*)&Kbase[(size_t)(j0 + r) * Dd + kk4];
            }

            // ---- Q-phase (every iter; iter 0 reads slots0) ----
            {
                wait_ge(&g_slot_done[b], 3u * iter);
                if (w < nr) {
                    int row = qs0 + w;
                    const float* src = g_slots + ((size_t)b * Ss + row) * Dd;
                    float v[8]; float s = 0.f;
                    #pragma unroll
                    for (int u = 0; u < 8; u++) { v[u] = __ldcg(&src[l + 32 * u]); s += v[u]; }
                    s = warp_sum(s);
                    float m = s * (1.0f / Dd);
                    float vs = 0.f;
                    #pragma unroll
                    for (int u = 0; u < 8; u++) { v[u] -= m; vs += v[u] * v[u]; }
                    vs = warp_sum(vs);
                    float iv = rsqrtf(vs * (1.0f / Dd) + LN_EPS);
                    #pragma unroll
                    for (int u = 0; u < 8; u++) {
                        int k = l + 32 * u;
                        sm.d.xq[w][k] = v[u] * iv * g_sl[k] + be_sl[k];
                    }
                }
                if (nr < 4 && w == 4) {
                    #pragma unroll
                    for (int u = 0; u < 8; u++) sm.d.xq[3][l + 32 * u] = 0.f;
                }
                __syncthreads();
                {
                    int c = t;
                    float acc[4];
                    float bqc = bq[c];
                    #pragma unroll
                    for (int r = 0; r < 4; r++) acc[r] = bqc;
                    const float4* wp = g_WqT4 + c;
                    float4 cw = ldcg4(wp);
                    for (int kq = 0; kq < 64; kq++) {
                        float4 nw = ldcg4(wp + (size_t)(kq < 63 ? kq + 1 : 63) * Dd);
                        int k = 4 * kq;
                        #pragma unroll
                        for (int r = 0; r < 4; r++) {
                            float4 x4 = *(const float4*)&sm.d.xq[r][k];
                            acc[r] = fmaf(x4.x, cw.x, acc[r]);
                            acc[r] = fmaf(x4.y, cw.y, acc[r]);
                            acc[r] = fmaf(x4.z, cw.z, acc[r]);
                            acc[r] = fmaf(x4.w, cw.w, acc[r]);
                        }
                        cw = nw;
                    }
                    for (int r = 0; r < nr; r++)
                        g_Q[((size_t)b * Ss + qs0 + r) * Dd + c] = acc[r];
                }
                signal(&g_q_done[b]);
                wait_ge(&g_q_done[b], 6u * (iter + 1));
            }

            // ---- dots main: 4 chunks of 64 cols, ping-pong double buffer ----
            for (int idx = t; idx < Ss * 16; idx += 256) {
                int r = idx >> 4, kk4 = (idx & 15) * 4;
                *(float4*)&sm.d.Qs[0][r][kk4] =
                    __ldcg((const float4*)&g_Q[((size_t)b * Ss + r) * Dd + kk4]);
            }
            __syncthreads();
            u64 A0 = 0ULL, A1 = 0ULL, A2 = 0ULL;
            #pragma unroll
            for (int ch = 0; ch < 4; ch++) {
                int cb = ch & 1, nb = cb ^ 1;
                if (ch < 3) {
                    int k0 = (ch + 1) * 64;
                    for (int idx = t; idx < 32 * 16; idx += 256) {
                        int r = idx >> 4, kk4 = (idx & 15) * 4;
                        *(float4*)&sm.d.Ks[nb][r][kk4] =
                            *(const float4*)&Kbase[(size_t)(j0 + r) * Dd + k0 + kk4];
                    }
                    for (int idx = t; idx < Ss * 16; idx += 256) {
                        int r = idx >> 4, kk4 = (idx & 15) * 4;
                        *(float4*)&sm.d.Qs[nb][r][kk4] =
                            __ldcg((const float4*)&g_Q[((size_t)b * Ss + r) * Dd + k0 + kk4]);
                    }
                }
                #pragma unroll
                for (int kk = 0; kk < 64; kk += 4) {
                    ulonglong2 kp = *(const ulonglong2*)&sm.d.Ks[cb][jj][kk];
                    ulonglong2 q0 = *(const ulonglong2*)&sm.d.Qs[cb][i0][kk];
                    ulonglong2 q1 = *(const ulonglong2*)&sm.d.Qs[cb][i1][kk];
                    fma2(A0, kp.x, q0.x); fma2(A0, kp.y, q0.y);
                    fma2(A1, kp.x, q1.x); fma2(A1, kp.y, q1.y);
                    if (has2) {
                        ulonglong2 q2 = *(const ulonglong2*)&sm.d.Qs[cb][i2][kk];
                        fma2(A2, kp.x, q2.x); fma2(A2, kp.y, q2.y);
                    }
                }
                __syncthreads();
            }
            float2 s0 = unpk(A0), s1 = unpk(A1);
            sm.d.ds[jj][i0] = (s0.x + s0.y) * 0.0625f;
            sm.d.ds[jj][i1] = (s1.x + s1.y) * 0.0625f;
            if (has2) { float2 s2 = unpk(A2); sm.d.ds[jj][i2] = (s2.x + s2.y) * 0.0625f; }
            __syncthreads();
            for (int q = w; q < 32; q += 8) {
                float v = (l < Ss) ? sm.d.ds[q][l] : -3.4e38f;
                float mx = warp_max(v);
                float e = (l < Ss) ? expf(v - mx) : 0.f;
                float smv = warp_sum(e);
                if (l < Ss) {
                    float a = e / smv + EPSs;
                    g_At[((size_t)b * Nn + j0 + q) * Ss + l] = a;
                    if (it == 2)
                        out_attn[(((size_t)b * NFr + f) * Ss + l) * Nn + j0 + q] = a;
                }
            }
            __syncthreads();
            signal(&g_dots_done[b]);
        }
    } else {
        // ================= SLOT block =================
        int i0 = (role - 6) * RS;
        int c = t;
        for (int iter = 0; iter < NFr * 3; iter++) {
            int f = iter / 3;

            // ---- EARLY: h0 + h-side GRU gates (overlaps dots+Q) ----
            float h0lo[4], h0hi[4];
            #pragma unroll
            for (int p = 0; p < 4; p++) {
                int rlo = 2 * p, rhi = (2 * p + 1 < RS) ? 2 * p + 1 : RS - 1;
                h0lo[p] = g_slots[((size_t)b * Ss + i0 + rlo) * Dd + c];
                h0hi[p] = g_slots[((size_t)b * Ss + i0 + rhi) * Dd + c];
            }
            #pragma unroll
            for (int p = 0; p < 4; p++) sm.s.hsp[p][c] = make_float2(h0lo[p], h0hi[p]);
            __syncthreads();

            u64 a_hr[4], a_hz[4], a_hn[4];
            #pragma unroll
            for (int p = 0; p < 4; p++) { a_hr[p] = 0ULL; a_hz[p] = 0ULL; a_hn[p] = 0ULL; }
            {
                const float4* wh4 = g_WhhT4 + c;
                float4 cvr = ldcg4(wh4), cvz = ldcg4(wh4 + Dd), cvn = ldcg4(wh4 + 2 * Dd);
                for (int kq = 0; kq < 64; kq++) {
                    size_t nx = (size_t)(kq < 63 ? kq + 1 : 63) * (3 * Dd);
                    float4 nvr = ldcg4(wh4 + nx), nvz = ldcg4(wh4 + nx + Dd),
                           nvn = ldcg4(wh4 + nx + 2 * Dd);
                    int k = 4 * kq;
                    #pragma unroll
                    for (int p = 0; p < 4; p++) {
                        ulonglong2 h2a = *(const ulonglong2*)&sm.s.hsp[p][k];
                        ulonglong2 h2b = *(const ulonglong2*)&sm.s.hsp[p][k + 2];
                        fma2(a_hr[p], h2a.x, dup2(cvr.x)); fma2(a_hr[p], h2a.y, dup2(cvr.y));
                        fma2(a_hr[p], h2b.x, dup2(cvr.z)); fma2(a_hr[p], h2b.y, dup2(cvr.w));
                        fma2(a_hz[p], h2a.x, dup2(cvz.x)); fma2(a_hz[p], h2a.y, dup2(cvz.y));
                        fma2(a_hz[p], h2b.x, dup2(cvz.z)); fma2(a_hz[p], h2b.y, dup2(cvz.w));
                        fma2(a_hn[p], h2a.x, dup2(cvn.x)); fma2(a_hn[p], h2a.y, dup2(cvn.y));
                        fma2(a_hn[p], h2b.x, dup2(cvn.z)); fma2(a_hn[p], h2b.y, dup2(cvn.w));
                    }
                    cvr = nvr; cvz = nvz; cvn = nvn;
                }
            }

            wait_ge(&g_dots_done[b], 6u * (iter + 1));
            if (f >= 2) wait_ge(&g_kv_ready[b * NFr + f], 8u);

            // Phase A: stage attn + row sums
            for (int idx = t; idx < 8 * Nn; idx += 256) {
                int lr = idx & 7, j = idx >> 3;
                int row = (lr < 7) ? lr : 6;
                ((float*)sm.s.asp)[((size_t)(lr >> 1) * Nn + j) * 2 + (lr & 1)] =
                    __ldcg(&g_At[((size_t)b * Nn + j) * Ss + i0 + row]);
            }
            __syncthreads();
            {
                int p = w >> 1, e = w & 1;
                float s = 0.f;
                #pragma unroll
                for (int u = 0; u < Nn / 32; u++)
                    s += ((const float*)sm.s.asp)[((size_t)p * Nn + l + 32 * u) * 2 + e];
                s = warp_sum(s);
                if (l == 0) sm.s.inv_[w] = 1.0f / s;
            }
            __syncthreads();

            // Phase B: updates = (A/rowsum) @ V
            u64 accU[4];
            #pragma unroll
            for (int p = 0; p < 4; p++) accU[p] = 0ULL;
            const float4* vp4 = g_V4 + (((size_t)b * NFr + f) * (Nn / 4)) * Dd + c;
            float4 cvv = vp4[0];
            for (int nq = 0; nq < Nn / 4; nq++) {
                float4 nvv = vp4[(size_t)(nq < Nn / 4 - 1 ? nq + 1 : nq) * Dd];
                int j = 4 * nq;
                u64 vd0 = dup2(cvv.x), vd1 = dup2(cvv.y);
                u64 vd2 = dup2(cvv.z), vd3 = dup2(cvv.w);
                #pragma unroll
                for (int p = 0; p < 4; p++) {
                    ulonglong2 a2a = *(const ulonglong2*)&sm.s.asp[p][j];
                    ulonglong2 a2b = *(const ulonglong2*)&sm.s.asp[p][j + 2];
                    fma2(accU[p], a2a.x, vd0); fma2(accU[p], a2a.y, vd1);
                    fma2(accU[p], a2b.x, vd2); fma2(accU[p], a2b.y, vd3);
                }
                cvv = nvv;
            }
            #pragma unroll
            for (int p = 0; p < 4; p++) {
                float2 u2 = unpk(accU[p]);
                sm.s.usp[p][c] = make_float2(u2.x * sm.s.inv_[2 * p],
                                             u2.y * sm.s.inv_[2 * p + 1]);
            }
            __syncthreads();

            // Phase C: u-side GRU gates
            u64 a_ir[4], a_iz[4], a_in[4];
            #pragma unroll
            for (int p = 0; p < 4; p++) { a_ir[p] = 0ULL; a_iz[p] = 0ULL; a_in[p] = 0ULL; }
            {
                const float4* wi4 = g_WihT4 + c;
                float4 cwr = ldcg4(wi4), cwz = ldcg4(wi4 + Dd), cwn = ldcg4(wi4 + 2 * Dd);
                for (int kq = 0; kq < 64; kq++) {
                    size_t nx = (size_t)(kq < 63 ? kq + 1 : 63) * (3 * Dd);
                    float4 nwr = ldcg4(wi4 + nx), nwz = ldcg4(wi4 + nx + Dd),
                           nwn = ldcg4(wi4 + nx + 2 * Dd);
                    int k = 4 * kq;
                    #pragma unroll
                    for (int p = 0; p < 4; p++) {
                        ulonglong2 u2a = *(const ulonglong2*)&sm.s.usp[p][k];
                        ulonglong2 u2b = *(const ulonglong2*)&sm.s.usp[p][k + 2];
                        fma2(a_ir[p], u2a.x, dup2(cwr.x)); fma2(a_ir[p], u2a.y, dup2(cwr.y));
                        fma2(a_ir[p], u2b.x, dup2(cwr.z)); fma2(a_ir[p], u2b.y, dup2(cwr.w));
                        fma2(a_iz[p], u2a.x, dup2(cwz.x)); fma2(a_iz[p], u2a.y, dup2(cwz.y));
                        fma2(a_iz[p], u2b.x, dup2(cwz.z)); fma2(a_iz[p], u2b.y, dup2(cwz.w));
                        fma2(a_in[p], u2a.x, dup2(cwn.x)); fma2(a_in[p], u2a.y, dup2(cwn.y));
                        fma2(a_in[p], u2b.x, dup2(cwn.z)); fma2(a_in[p], u2b.y, dup2(cwn.w));
                    }
                    cwr = nwr; cwz = nwz; cwn = nwn;
                }
            }
            float bir = b_ih[c], biz = b_ih[Dd + c], bin = b_ih[2 * Dd + c];
            float bhr = b_hh[c], bhz = b_hh[Dd + c], bhn = b_hh[2 * Dd + c];
            float hnlo[4], hnhi[4];
            #pragma unroll
            for (int p = 0; p < 4; p++) {
                float2 ir2 = unpk(a_ir[p]), iz2 = unpk(a_iz[p]), in2 = unpk(a_in[p]);
                float2 hr2 = unpk(a_hr[p]), hz2 = unpk(a_hz[p]), hn2 = unpk(a_hn[p]);
                {
                    float rg = 1.f / (1.f + expf(-(ir2.x + bir + hr2.x + bhr)));
                    float zg = 1.f / (1.f + expf(-(iz2.x + biz + hz2.x + bhz)));
                    float ng = tanhf(in2.x + bin + rg * (hn2.x + bhn));
                    hnlo[p] = (1.f - zg) * ng + zg * h0lo[p];
                }
                {
                    float rg = 1.f / (1.f + expf(-(ir2.y + bir + hr2.y + bhr)));
                    float zg = 1.f / (1.f + expf(-(iz2.y + biz + hz2.y + bhz)));
                    float ng = tanhf(in2.y + bin + rg * (hn2.y + bhn));
                    hnhi[p] = (1.f - zg) * ng + zg * h0hi[p];
                }
            }
            __syncthreads();
            #pragma unroll
            for (int p = 0; p < 4; p++) sm.s.usp[p][c] = make_float2(hnlo[p], hnhi[p]);
            __syncthreads();

            // Phase D: LN(hnew; g_ff) -> hsp
            {
                int p = w >> 1, e = w & 1;
                float v[8]; float s = 0.f;
                #pragma unroll
                for (int u = 0; u < 8; u++) {
                    v[u] = ((const float*)sm.s.usp)[((size_t)p * Dd + l + 32 * u) * 2 + e];
                    s += v[u];
                }
                s = warp_sum(s);
                float m = s * (1.0f / Dd);
                float vs = 0.f;
                #pragma unroll
                for (int u = 0; u < 8; u++) { v[u] -= m; vs += v[u] * v[u]; }
                vs = warp_sum(vs);
                float iv = rsqrtf(vs * (1.0f / Dd) + LN_EPS);
                #pragma unroll
                for (int u = 0; u < 8; u++) {
                    int k = l + 32 * u;
                    ((float*)sm.s.hsp)[((size_t)p * Dd + k) * 2 + e] =
                        v[u] * iv * g_ff[k] + be_ff[k];
                }
            }
            __syncthreads();

            // Phase E: FF = relu(LN @ W1T + b1) -> fsp
            {
                u64 aF[4];
                #pragma unroll
                for (int p = 0; p < 4; p++) aF[p] = 0ULL;
                const float4* wp = g_W1T4 + c;
                float4 cw = ldcg4(wp);
                for (int kq = 0; kq < 64; kq++) {
                    float4 nw = ldcg4(wp + (size_t)(kq < 63 ? kq + 1 : 63) * Dd);
                    int k = 4 * kq;
                    u64 d0 = dup2(cw.x), d1 = dup2(cw.y), d2 = dup2(cw.z), d3 = dup2(cw.w);
                    #pragma unroll
                    for (int p = 0; p < 4; p++) {
                        ulonglong2 x2a = *(const ulonglong2*)&sm.s.hsp[p][k];
                        ulonglong2 x2b = *(const ulonglong2*)&sm.s.hsp[p][k + 2];
                        fma2(aF[p], x2a.x, d0); fma2(aF[p], x2a.y, d1);
                        fma2(aF[p], x2b.x, d2); fma2(aF[p], x2b.y, d3);
                    }
                    cw = nw;
                }
                float b1c = b1[c];
                #pragma unroll
                for (int p = 0; p < 4; p++) {
                    float2 f2 = unpk(aF[p]);
                    sm.s.fsp[p][c] = make_float2(fmaxf(f2.x + b1c, 0.f),
                                                 fmaxf(f2.y + b1c, 0.f));
                }
            }
            __syncthreads();

            // Phase F: slots_new = hnew + fsp @ W2T + b2 -> global; then signal
            {
                u64 aO[4];
                #pragma unroll
                for (int p = 0; p < 4; p++) aO[p] = 0ULL;
                const float4* wp = g_W2T4 + c;
                float4 cw = ldcg4(wp);
                for (int kq = 0; kq < 64; kq++) {
                    float4 nw = ldcg4(wp + (size_t)(kq < 63 ? kq + 1 : 63) * Dd);
                    int k = 4 * kq;
                    u64 d0 = dup2(cw.x), d1 = dup2(cw.y), d2 = dup2(cw.z), d3 = dup2(cw.w);
                    #pragma unroll
                    for (int p = 0; p < 4; p++) {
                        ulonglong2 x2a = *(const ulonglong2*)&sm.s.fsp[p][k];
                        ulonglong2 x2b = *(const ulonglong2*)&sm.s.fsp[p][k + 2];
                        fma2(aO[p], x2a.x, d0); fma2(aO[p], x2a.y, d1);
                        fma2(aO[p], x2b.x, d2); fma2(aO[p], x2b.y, d3);
                    }
                    cw = nw;
                }
                float b2c = b2[c];
                bool last = (iter == NFr * 3 - 1);
                #pragma unroll
                for (int p = 0; p < 4; p++) {
                    float2 o2 = unpk(aO[p]);
                    float snlo = hnlo[p] + o2.x + b2c;
                    float snhi = hnhi[p] + o2.y + b2c;
                    int rlo = i0 + 2 * p;
                    g_slots[((size_t)b * Ss + rlo) * Dd + c] = snlo;
                    if (2 * p + 1 < RS) g_slots[((size_t)b * Ss + rlo + 1) * Dd + c] = snhi;
                    if (last) {
                        if (rlo < NA)
                            out_slots[((size_t)b * NA + rlo) * Dd + c] = snlo;
                        if (2 * p + 1 < RS && rlo + 1 < NA)
                            out_slots[((size_t)b * NA + rlo + 1) * Dd + c] = snhi;
                    }
                }
            }
            signal(&g_slot_done[b]);
        }
    }
}

// ---------------- launch ------------------------------------------------------
extern "C" void kernel_launch(void* const* d_in, const int* in_sizes, int n_in,
                              void* d_out, int out_size) {
    const float* inputs = (const float*)d_in[0];
    const float* noise  = (const float*)d_in[1];
    const float* mu     = (const float*)d_in[2];
    const float* sigma  = (const float*)d_in[3];
    const float* Wq     = (const float*)d_in[4];
    const float* bq     = (const float*)d_in[5];
    const float* Wk     = (const float*)d_in[6];
    const float* bk     = (const float*)d_in[7];
    const float* Wv     = (const float*)d_in[8];
    const float* bv     = (const float*)d_in[9];
    const float* W1     = (const float*)d_in[10];
    const float* b1     = (const float*)d_in[11];
    const float* W2     = (const float*)d_in[12];
    const float* b2     = (const float*)d_in[13];
    const float* W_ih   = (const float*)d_in[14];
    const float* b_ih   = (const float*)d_in[15];
    const float* W_hh   = (const float*)d_in[16];
    const float* b_hh   = (const float*)d_in[17];
    const float* gin    = (const float*)d_in[18];
    const float* bein   = (const float*)d_in[19];
    const float* gsl    = (const float*)d_in[20];
    const float* besl   = (const float*)d_in[21];
    const float* gff    = (const float*)d_in[22];
    const float* beff   = (const float*)d_in[23];

    float* out = (float*)d_out;
    float* out_attn = out + (size_t)Bz * NA * Dd;

    setup_kernel<<<344, dim3(32, 8)>>>(Wq, Wk, Wv, W1, W2, W_ih, W_hh,
                                       noise, mu, sigma);
    kv01_kernel<<<512, 256>>>(inputs, gin, bein, bk, bv);
    persist_kernel<<<Bz * 9, 256>>>(out, out_attn, inputs, gin, bein, bk, bv,
                                    b_ih, b_hh, gff, beff,
                                    b1, b2, gsl, besl, bq);
}